// round 1
// baseline (speedup 1.0000x reference)
#include <cuda_runtime.h>
#include <math.h>

// Shapes (fixed for this problem)
#define Bb   8
#define Ll   512
#define Mm   512
#define Hh   8
#define DKk  128
#define DVv  128
#define Ss   512
#define DMm  1024
#define WREC 1024
#define TQ   8

#define INVTAU 0.08838834764831845f   // 1/sqrt(128)

// ---------------- scratch (device globals; no allocation allowed) ------------
__device__ float g_xt  [Bb*Ll*DMm];          // 16 MB  normalized input
__device__ float g_qraw[Bb*Ll*Hh*DKk];       // 16 MB  x_t @ W_q
__device__ float g_kvg [Bb*Ll*3072];         // 48 MB  x_t @ W_kvg
__device__ float g_qn  [Bb*Hh*Ll*DKk];       // 16 MB  LN(q), (b,h,l,d)
__device__ float g_kn  [Bb*Hh*Ll*DKk];       // 16 MB  LN(k), (b,h,l,d)
__device__ float g_g   [Bb*Ll*Hh*DVv];       // 16 MB  silu gate
__device__ float g_rk  [Bb*Hh*WREC*DKk];     // 32 MB  recent_k_hat
__device__ float g_rv  [Bb*Hh*WREC*DVv];     // 32 MB  recent_v
__device__ float g_wvg [Bb*Ll*Hh*DVv];       // 16 MB  wv * g
__device__ int   g_z   [Bb*Hh*Ll];           // VQ indices

// ---------------- reductions -------------------------------------------------
__device__ __forceinline__ float blockReduceSum256(float v, float* sh) {
    #pragma unroll
    for (int o = 16; o > 0; o >>= 1) v += __shfl_xor_sync(0xffffffffu, v, o);
    __syncthreads();
    if ((threadIdx.x & 31) == 0) sh[threadIdx.x >> 5] = v;
    __syncthreads();
    float r = 0.f;
    #pragma unroll
    for (int i = 0; i < 8; i++) r += sh[i];
    return r;
}

__device__ __forceinline__ float blockReduceSum128(float v, float* sh) {
    #pragma unroll
    for (int o = 16; o > 0; o >>= 1) v += __shfl_xor_sync(0xffffffffu, v, o);
    __syncthreads();
    if ((threadIdx.x & 31) == 0) sh[threadIdx.x >> 5] = v;
    __syncthreads();
    return sh[0] + sh[1] + sh[2] + sh[3];
}

// ---------------- 1) LayerNorm of input (rows of 1024) -----------------------
__global__ void ln_input_kernel(const float* __restrict__ x) {
    __shared__ float sh[8];
    size_t base = (size_t)blockIdx.x * DMm;
    float lv[4]; float s = 0.f;
    #pragma unroll
    for (int j = 0; j < 4; j++) { lv[j] = x[base + threadIdx.x + j*256]; s += lv[j]; }
    float mu = blockReduceSum256(s, sh) * (1.f/1024.f);
    float s2 = 0.f;
    #pragma unroll
    for (int j = 0; j < 4; j++) { float d = lv[j] - mu; s2 += d*d; }
    float var = blockReduceSum256(s2, sh) * (1.f/1024.f);
    float rstd = rsqrtf(var + 1e-6f);
    #pragma unroll
    for (int j = 0; j < 4; j++) g_xt[base + threadIdx.x + j*256] = (lv[j]-mu)*rstd;
}

// ---------------- 2) fp32 tiled GEMM: C[MxN] = A[MxK] @ B[KxN] ---------------
// BM=128, BN=64, BK=16, blockDim(16,16), 8x4 microtile
__global__ void gemm_kernel(const float* __restrict__ A, const float* __restrict__ B,
                            float* __restrict__ C, int M, int N, int K) {
    __shared__ float As[16][129];
    __shared__ float Bs[16][64];
    int tid  = threadIdx.y * 16 + threadIdx.x;
    int row0 = blockIdx.y * 128;
    int col0 = blockIdx.x * 64;
    float acc[8][4];
    #pragma unroll
    for (int i = 0; i < 8; i++)
        #pragma unroll
        for (int j = 0; j < 4; j++) acc[i][j] = 0.f;

    for (int k0 = 0; k0 < K; k0 += 16) {
        #pragma unroll
        for (int j = 0; j < 8; j++) {
            int idx = tid + j*256;
            int r = idx >> 4, c = idx & 15;
            As[c][r] = A[(size_t)(row0 + r)*K + k0 + c];
        }
        #pragma unroll
        for (int j = 0; j < 4; j++) {
            int idx = tid + j*256;
            int r = idx >> 6, c = idx & 63;
            Bs[r][c] = B[(size_t)(k0 + r)*N + col0 + c];
        }
        __syncthreads();
        #pragma unroll
        for (int kk = 0; kk < 16; kk++) {
            float a[8], bb[4];
            #pragma unroll
            for (int i = 0; i < 8; i++) a[i] = As[kk][threadIdx.y*8 + i];
            #pragma unroll
            for (int j = 0; j < 4; j++) bb[j] = Bs[kk][threadIdx.x*4 + j];
            #pragma unroll
            for (int i = 0; i < 8; i++)
                #pragma unroll
                for (int j = 0; j < 4; j++) acc[i][j] += a[i]*bb[j];
        }
        __syncthreads();
    }
    #pragma unroll
    for (int i = 0; i < 8; i++)
        #pragma unroll
        for (int j = 0; j < 4; j++)
            C[(size_t)(row0 + threadIdx.y*8 + i)*N + col0 + threadIdx.x*4 + j] = acc[i][j];
}

// ---------------- 3) per-head LN of q and k, v copy, gate --------------------
// grid (B*L, H), 128 threads
__global__ void qkln_kernel() {
    __shared__ float sh[4];
    int bl = blockIdx.x, h = blockIdx.y, t = threadIdx.x;
    int b = bl >> 9, l = bl & 511;
    size_t bh = (size_t)(b*Hh + h);

    float x  = g_qraw[(size_t)bl*1024 + h*128 + t];
    float mu = blockReduceSum128(x, sh) * (1.f/128.f);
    float d  = x - mu;
    float var = blockReduceSum128(d*d, sh) * (1.f/128.f);
    g_qn[(bh*Ll + l)*128 + t] = d * rsqrtf(var + 1e-6f);

    x  = g_kvg[(size_t)bl*3072 + h*128 + t];
    mu = blockReduceSum128(x, sh) * (1.f/128.f);
    d  = x - mu;
    var = blockReduceSum128(d*d, sh) * (1.f/128.f);
    g_kn[(bh*Ll + l)*128 + t] = d * rsqrtf(var + 1e-6f);

    g_rv[(bh*WREC + Mm + l)*128 + t] = g_kvg[(size_t)bl*3072 + 1024 + h*128 + t];

    float gx = g_kvg[(size_t)bl*3072 + 2048 + h*128 + t];
    g_g[(size_t)bl*1024 + h*128 + t] = gx / (1.f + __expf(-gx));
}

// ---------------- 4) VQ argmin over 512 codes --------------------------------
// grid (B*H, L/16), 256 threads; each block: 16 k-rows vs full codebook of head
__global__ void vq_kernel(const float* __restrict__ codebook) {
    __shared__ float ks[16][128];
    __shared__ float redv[16][256];
    __shared__ int   redi[16][256];
    int bh = blockIdx.x, lt = blockIdx.y;
    int h  = bh & 7;
    int tid = threadIdx.x;
    #pragma unroll
    for (int j = 0; j < 8; j++) {
        int idx = tid + j*256;
        int r = idx >> 7, d = idx & 127;
        ks[r][d] = g_kn[((size_t)bh*Ll + lt*16 + r)*128 + d];
    }
    __syncthreads();

    float best[16]; int bidx[16];
    #pragma unroll
    for (int r = 0; r < 16; r++) { best[r] = 3.4e38f; bidx[r] = 0; }

    for (int s = tid; s < Ss; s += 256) {
        const float* c = codebook + ((size_t)h*Ss + s)*128;
        float cc = 0.f; float acc[16];
        #pragma unroll
        for (int r = 0; r < 16; r++) acc[r] = 0.f;
        for (int d = 0; d < 128; d++) {
            float cv = c[d];
            cc += cv*cv;
            #pragma unroll
            for (int r = 0; r < 16; r++) acc[r] += cv * ks[r][d];
        }
        #pragma unroll
        for (int r = 0; r < 16; r++) {
            float d2 = cc - 2.f*acc[r];   // ||k||^2 constant per row: irrelevant to argmin
            if (d2 < best[r]) { best[r] = d2; bidx[r] = s; }
        }
    }
    #pragma unroll
    for (int r = 0; r < 16; r++) { redv[r][tid] = best[r]; redi[r][tid] = bidx[r]; }
    __syncthreads();

    int warp = tid >> 5, lane = tid & 31;
    for (int r = warp*2; r < warp*2 + 2; r++) {
        float bv = 3.4e38f; int bi = 0x7fffffff;
        for (int t = lane; t < 256; t += 32) {
            float v = redv[r][t]; int i = redi[r][t];
            if (v < bv || (v == bv && i < bi)) { bv = v; bi = i; }
        }
        #pragma unroll
        for (int o = 16; o > 0; o >>= 1) {
            float ov = __shfl_xor_sync(0xffffffffu, bv, o);
            int   oi = __shfl_xor_sync(0xffffffffu, bi, o);
            if (ov < bv || (ov == bv && oi < bi)) { bv = ov; bi = oi; }
        }
        if (lane == 0) g_z[(size_t)bh*Ll + lt*16 + r] = bi;
    }
}

// ---------------- 5) assemble recent buffers ---------------------------------
__global__ void assemble_kernel(const float* __restrict__ xlk, const float* __restrict__ xlv,
                                const float* __restrict__ codebook) {
    for (int e = blockIdx.x*blockDim.x + threadIdx.x; e < Bb*Hh*Mm*DKk;
         e += gridDim.x*blockDim.x) {
        int bh  = e >> 16;           // M*DK = 65536
        int rem = e & 65535;
        int m = rem >> 7, d = rem & 127;
        size_t dst = ((size_t)bh*WREC + m)*128 + d;
        g_rk[dst] = xlk[e];
        g_rv[dst] = xlv[e];
        // k_hat gather (l has same decode range as m)
        int s = g_z[(size_t)bh*Ll + m];
        int h = bh & 7;
        g_rk[((size_t)bh*WREC + Mm + m)*128 + d] = codebook[((size_t)h*Ss + s)*128 + d];
    }
}

// ---------------- 6) fused attention -----------------------------------------
// grid (L/TQ, H, B), 256 threads, dynamic smem = (2*TQ*128 + TQ*1536 + TQ)*4
__global__ void attn_kernel(const float* __restrict__ xu, const float* __restrict__ xv,
                            const float* __restrict__ xlr, const float* __restrict__ codebook,
                            const float* __restrict__ aggU, const float* __restrict__ aggL) {
    extern __shared__ float sm[];
    float* qu_s = sm;                      // TQ*128
    float* qv_s = sm + TQ*128;             // TQ*128
    float* sc   = sm + 2*TQ*128;           // TQ*1536
    float* invd = sc + TQ*1536;            // TQ

    int l0 = blockIdx.x * TQ;
    int h  = blockIdx.y;
    int b  = blockIdx.z;
    size_t bh = (size_t)(b*Hh + h);
    int tid = threadIdx.x;

    for (int i = tid; i < TQ*128; i += 256) {
        int q = i >> 7, d = i & 127;
        float qval = g_qn[(bh*Ll + l0 + q)*128 + d];
        qu_s[i] = qval + xu[h*128 + d];
        qv_s[i] = qval + xv[h*128 + d];
    }
    __syncthreads();

    // AC: qu . recent_k_hat
    for (int w = tid; w < WREC; w += 256) {
        const float* kr = g_rk + (bh*WREC + w)*128;
        float acc[TQ];
        #pragma unroll
        for (int q = 0; q < TQ; q++) acc[q] = 0.f;
        for (int d = 0; d < 128; d++) {
            float kv = kr[d];
            #pragma unroll
            for (int q = 0; q < TQ; q++) acc[q] += kv * qu_s[q*128 + d];
        }
        #pragma unroll
        for (int q = 0; q < TQ; q++) sc[q*1536 + w] = acc[q] * INVTAU;
    }
    // cache: qu . codebook + log(agg_lower)
    for (int s = tid; s < Ss; s += 256) {
        float al = aggL[bh*Ss + s];
        float bias = (al > 0.f) ? logf(fmaxf(al, 1e-30f)) : -1e30f;
        const float* cr = codebook + ((size_t)h*Ss + s)*128;
        float acc[TQ];
        #pragma unroll
        for (int q = 0; q < TQ; q++) acc[q] = 0.f;
        for (int d = 0; d < 128; d++) {
            float cv = cr[d];
            #pragma unroll
            for (int q = 0; q < TQ; q++) acc[q] += cv * qu_s[q*128 + d];
        }
        #pragma unroll
        for (int q = 0; q < TQ; q++) sc[q*1536 + WREC + s] = acc[q] * INVTAU + bias;
    }
    __syncthreads();

    // BD: rel-shift term.  sc_bd[l,w] = qv . xl_r[h, w + 511 - l]
    for (int j = tid; j < WREC; j += 256) {
        const float* rr = xlr + ((size_t)h*WREC + j)*128;
        float acc[TQ];
        #pragma unroll
        for (int q = 0; q < TQ; q++) acc[q] = 0.f;
        for (int d = 0; d < 128; d++) {
            float rv_ = rr[d];
            #pragma unroll
            for (int q = 0; q < TQ; q++) acc[q] += rv_ * qv_s[q*128 + d];
        }
        #pragma unroll
        for (int q = 0; q < TQ; q++) {
            int w = j - 511 + l0 + q;
            if (w >= 0 && w < WREC) sc[q*1536 + w] += acc[q] * INVTAU;
        }
    }
    __syncthreads();

    // softmax: one warp per query, joint over 1536 scores (mask w > l+M)
    {
        int wq = tid >> 5, lane = tid & 31;
        int limit = l0 + wq + Mm;
        float m = -3.4e38f;
        for (int i = lane; i < 1536; i += 32) {
            float v = sc[wq*1536 + i];
            if (i < WREC && i > limit) v = -1e30f;
            m = fmaxf(m, v);
        }
        #pragma unroll
        for (int o = 16; o > 0; o >>= 1) m = fmaxf(m, __shfl_xor_sync(0xffffffffu, m, o));
        float ssum = 0.f;
        for (int i = lane; i < 1536; i += 32) {
            float v = sc[wq*1536 + i];
            float p = (i < WREC && i > limit) ? 0.f : __expf(v - m);
            sc[wq*1536 + i] = p;
            ssum += p;
        }
        #pragma unroll
        for (int o = 16; o > 0; o >>= 1) ssum += __shfl_xor_sync(0xffffffffu, ssum, o);
        if (lane == 0) invd[wq] = 1.f / ssum;
    }
    __syncthreads();

    // weighted values: 256 threads = (dim 0..127) x (key-half 0/1)
    int d = tid & 127, half = tid >> 7;
    float acc[TQ];
    #pragma unroll
    for (int q = 0; q < TQ; q++) acc[q] = 0.f;
    int w0 = half * 768;
    for (int w = w0; w < w0 + 768; w++) {
        float vv = (w < WREC) ? g_rv[(bh*WREC + w)*128 + d]
                              : aggU[(bh*Ss + (w - WREC))*128 + d];
        #pragma unroll
        for (int q = 0; q < TQ; q++) acc[q] += sc[q*1536 + w] * vv;
    }
    if (half == 1) {
        #pragma unroll
        for (int q = 0; q < TQ; q++) qv_s[q*128 + d] = acc[q];   // reuse qv_s as scratch
    }
    __syncthreads();
    if (half == 0) {
        #pragma unroll
        for (int q = 0; q < TQ; q++) {
            float tot = (acc[q] + qv_s[q*128 + d]) * invd[q];
            size_t oi = ((size_t)(b*Ll + l0 + q))*1024 + h*128 + d;
            g_wvg[oi] = tot * g_g[oi];
        }
    }
}

// ---------------- launch ------------------------------------------------------
extern "C" void kernel_launch(void* const* d_in, const int* in_sizes, int n_in,
                              void* d_out, int out_size) {
    const float* input = (const float*)d_in[0];
    const float* xlk   = (const float*)d_in[2];
    const float* xlv   = (const float*)d_in[3];
    const float* aggU  = (const float*)d_in[4];
    const float* aggL  = (const float*)d_in[5];
    const float* Wq    = (const float*)d_in[6];
    const float* Wkvg  = (const float*)d_in[7];
    const float* Wres  = (const float*)d_in[8];
    const float* xu    = (const float*)d_in[9];
    const float* xv    = (const float*)d_in[10];
    const float* xlr   = (const float*)d_in[11];
    const float* cb    = (const float*)d_in[12];
    float* out = (float*)d_out;

    float *xt, *qraw, *kvg, *wvg;
    cudaGetSymbolAddress((void**)&xt,   g_xt);
    cudaGetSymbolAddress((void**)&qraw, g_qraw);
    cudaGetSymbolAddress((void**)&kvg,  g_kvg);
    cudaGetSymbolAddress((void**)&wvg,  g_wvg);

    dim3 thr(16, 16);

    ln_input_kernel<<<Bb*Ll, 256>>>(input);
    gemm_kernel<<<dim3(1024/64, 4096/128), thr>>>(xt, Wq,   qraw, 4096, 1024, 1024);
    gemm_kernel<<<dim3(3072/64, 4096/128), thr>>>(xt, Wkvg, kvg,  4096, 3072, 1024);
    qkln_kernel<<<dim3(Bb*Ll, Hh), 128>>>();
    vq_kernel<<<dim3(Bb*Hh, Ll/16), 256>>>(cb);
    assemble_kernel<<<4096, 256>>>(xlk, xlv, cb);

    const int attn_smem = (2*TQ*128 + TQ*1536 + TQ) * 4;   // 57376 B
    cudaFuncSetAttribute(attn_kernel, cudaFuncAttributeMaxDynamicSharedMemorySize, attn_smem);
    attn_kernel<<<dim3(Ll/TQ, Hh, Bb), 256, attn_smem>>>(xu, xv, xlr, cb, aggU, aggL);

    gemm_kernel<<<dim3(1024/64, 4096/128), thr>>>(wvg, Wres, out, 4096, 1024, 1024);
}

// round 2
// speedup vs baseline: 2.0972x; 2.0972x over previous
#include <cuda_runtime.h>
#include <math.h>

// Shapes (fixed for this problem)
#define Bb   8
#define Ll   512
#define Mm   512
#define Hh   8
#define DKk  128
#define DVv  128
#define Ss   512
#define DMm  1024
#define WREC 1024
#define TQ   8

#define INVTAU 0.08838834764831845f   // 1/sqrt(128)

// ---------------- scratch (device globals; no allocation allowed) ------------
__device__ float g_xt  [Bb*Ll*DMm];
__device__ float g_qraw[Bb*Ll*Hh*DKk];
__device__ float g_kvg [Bb*Ll*3072];
__device__ float g_qn  [Bb*Hh*Ll*DKk];
__device__ float g_kn  [Bb*Hh*Ll*DKk];
__device__ float g_g   [Bb*Ll*Hh*DVv];
__device__ float g_rk  [Bb*Hh*WREC*DKk];
__device__ float g_rv  [Bb*Hh*WREC*DVv];
__device__ float g_wvg [Bb*Ll*Hh*DVv];
__device__ int   g_z   [Bb*Hh*Ll];

// ---------------- reductions -------------------------------------------------
__device__ __forceinline__ float blockReduceSum256(float v, float* sh) {
    #pragma unroll
    for (int o = 16; o > 0; o >>= 1) v += __shfl_xor_sync(0xffffffffu, v, o);
    __syncthreads();
    if ((threadIdx.x & 31) == 0) sh[threadIdx.x >> 5] = v;
    __syncthreads();
    float r = 0.f;
    #pragma unroll
    for (int i = 0; i < 8; i++) r += sh[i];
    return r;
}

__device__ __forceinline__ float blockReduceSum128(float v, float* sh) {
    #pragma unroll
    for (int o = 16; o > 0; o >>= 1) v += __shfl_xor_sync(0xffffffffu, v, o);
    __syncthreads();
    if ((threadIdx.x & 31) == 0) sh[threadIdx.x >> 5] = v;
    __syncthreads();
    return sh[0] + sh[1] + sh[2] + sh[3];
}

// ---------------- 1) LayerNorm of input (rows of 1024) -----------------------
__global__ void ln_input_kernel(const float* __restrict__ x) {
    __shared__ float sh[8];
    size_t base = (size_t)blockIdx.x * DMm;
    float lv[4]; float s = 0.f;
    #pragma unroll
    for (int j = 0; j < 4; j++) { lv[j] = x[base + threadIdx.x + j*256]; s += lv[j]; }
    float mu = blockReduceSum256(s, sh) * (1.f/1024.f);
    float s2 = 0.f;
    #pragma unroll
    for (int j = 0; j < 4; j++) { float d = lv[j] - mu; s2 += d*d; }
    float var = blockReduceSum256(s2, sh) * (1.f/1024.f);
    float rstd = rsqrtf(var + 1e-6f);
    #pragma unroll
    for (int j = 0; j < 4; j++) g_xt[base + threadIdx.x + j*256] = (lv[j]-mu)*rstd;
}

// ---------------- 2) fp32 tiled GEMM: C[MxN] = A[MxK] @ B[KxN] ---------------
// 128x128 tile, BK=16, 256 threads, 8x8 microtile (cols split n0 / n0+64)
__global__ void __launch_bounds__(256, 2)
gemm_kernel(const float* __restrict__ A, const float* __restrict__ B,
            float* __restrict__ C, int M, int N, int K) {
    __shared__ float As[16][132];   // [k][m]
    __shared__ float Bs[16][132];   // [k][n]
    int tid  = threadIdx.x;
    int row0 = blockIdx.y * 128;
    int col0 = blockIdx.x * 128;
    int tx = tid & 15, ty = tid >> 4;

    float acc[8][8];
    #pragma unroll
    for (int i = 0; i < 8; i++)
        #pragma unroll
        for (int j = 0; j < 8; j++) acc[i][j] = 0.f;

    for (int k0 = 0; k0 < K; k0 += 16) {
        #pragma unroll
        for (int i = 0; i < 2; i++) {
            int f = tid + i*256;
            int r = f >> 2, c4 = f & 3;
            float4 v = *(const float4*)&A[(size_t)(row0 + r)*K + k0 + c4*4];
            As[c4*4+0][r] = v.x; As[c4*4+1][r] = v.y;
            As[c4*4+2][r] = v.z; As[c4*4+3][r] = v.w;
        }
        #pragma unroll
        for (int i = 0; i < 2; i++) {
            int f = tid + i*256;
            int r = f >> 5, c4 = f & 31;
            *(float4*)&Bs[r][c4*4] = *(const float4*)&B[(size_t)(k0 + r)*N + col0 + c4*4];
        }
        __syncthreads();
        #pragma unroll
        for (int kk = 0; kk < 16; kk++) {
            float a[8], bb[8];
            *(float4*)&a[0]  = *(float4*)&As[kk][ty*8];
            *(float4*)&a[4]  = *(float4*)&As[kk][ty*8 + 4];
            *(float4*)&bb[0] = *(float4*)&Bs[kk][tx*4];
            *(float4*)&bb[4] = *(float4*)&Bs[kk][64 + tx*4];
            #pragma unroll
            for (int i = 0; i < 8; i++)
                #pragma unroll
                for (int j = 0; j < 8; j++) acc[i][j] += a[i]*bb[j];
        }
        __syncthreads();
    }
    #pragma unroll
    for (int i = 0; i < 8; i++) {
        size_t crow = (size_t)(row0 + ty*8 + i)*N;
        *(float4*)&C[crow + col0 + tx*4]      = make_float4(acc[i][0], acc[i][1], acc[i][2], acc[i][3]);
        *(float4*)&C[crow + col0 + 64 + tx*4] = make_float4(acc[i][4], acc[i][5], acc[i][6], acc[i][7]);
    }
}

// ---------------- 3) per-head LN of q and k, v copy, gate --------------------
__global__ void qkln_kernel() {
    __shared__ float sh[4];
    int bl = blockIdx.x, h = blockIdx.y, t = threadIdx.x;
    int b = bl >> 9, l = bl & 511;
    size_t bh = (size_t)(b*Hh + h);

    float x  = g_qraw[(size_t)bl*1024 + h*128 + t];
    float mu = blockReduceSum128(x, sh) * (1.f/128.f);
    float d  = x - mu;
    float var = blockReduceSum128(d*d, sh) * (1.f/128.f);
    g_qn[(bh*Ll + l)*128 + t] = d * rsqrtf(var + 1e-6f);

    x  = g_kvg[(size_t)bl*3072 + h*128 + t];
    mu = blockReduceSum128(x, sh) * (1.f/128.f);
    d  = x - mu;
    var = blockReduceSum128(d*d, sh) * (1.f/128.f);
    g_kn[(bh*Ll + l)*128 + t] = d * rsqrtf(var + 1e-6f);

    g_rv[(bh*WREC + Mm + l)*128 + t] = g_kvg[(size_t)bl*3072 + 1024 + h*128 + t];

    float gx = g_kvg[(size_t)bl*3072 + 2048 + h*128 + t];
    g_g[(size_t)bl*1024 + h*128 + t] = gx / (1.f + __expf(-gx));
}

// ---------------- 4) VQ argmin over 512 codes (float4 codebook reads) --------
__global__ void vq_kernel(const float* __restrict__ codebook) {
    __shared__ float ks[16][128];
    __shared__ float redv[16][256];
    __shared__ int   redi[16][256];
    int bh = blockIdx.x, lt = blockIdx.y;
    int h  = bh & 7;
    int tid = threadIdx.x;
    #pragma unroll
    for (int j = 0; j < 2; j++) {
        int f = tid + j*256;
        int r = f >> 5, c4 = f & 31;
        *(float4*)&ks[r][c4*4] =
            *(const float4*)&g_kn[((size_t)bh*Ll + lt*16 + r)*128 + c4*4];
    }
    __syncthreads();

    float best[16]; int bidx[16];
    #pragma unroll
    for (int r = 0; r < 16; r++) { best[r] = 3.4e38f; bidx[r] = 0; }

    for (int s = tid; s < Ss; s += 256) {
        const float4* c = (const float4*)(codebook + ((size_t)h*Ss + s)*128);
        float cc = 0.f; float acc[16];
        #pragma unroll
        for (int r = 0; r < 16; r++) acc[r] = 0.f;
        #pragma unroll 4
        for (int d4 = 0; d4 < 32; d4++) {
            float4 cv = c[d4];
            cc += cv.x*cv.x + cv.y*cv.y + cv.z*cv.z + cv.w*cv.w;
            #pragma unroll
            for (int r = 0; r < 16; r++) {
                float4 kv = *(float4*)&ks[r][d4*4];
                acc[r] += cv.x*kv.x + cv.y*kv.y + cv.z*kv.z + cv.w*kv.w;
            }
        }
        #pragma unroll
        for (int r = 0; r < 16; r++) {
            float d2 = cc - 2.f*acc[r];
            if (d2 < best[r]) { best[r] = d2; bidx[r] = s; }
        }
    }
    #pragma unroll
    for (int r = 0; r < 16; r++) { redv[r][tid] = best[r]; redi[r][tid] = bidx[r]; }
    __syncthreads();

    int warp = tid >> 5, lane = tid & 31;
    for (int r = warp*2; r < warp*2 + 2; r++) {
        float bv = 3.4e38f; int bi = 0x7fffffff;
        for (int t = lane; t < 256; t += 32) {
            float v = redv[r][t]; int i = redi[r][t];
            if (v < bv || (v == bv && i < bi)) { bv = v; bi = i; }
        }
        #pragma unroll
        for (int o = 16; o > 0; o >>= 1) {
            float ov = __shfl_xor_sync(0xffffffffu, bv, o);
            int   oi = __shfl_xor_sync(0xffffffffu, bi, o);
            if (ov < bv || (ov == bv && oi < bi)) { bv = ov; bi = oi; }
        }
        if (lane == 0) g_z[(size_t)bh*Ll + lt*16 + r] = bi;
    }
}

// ---------------- 5) assemble recent buffers ---------------------------------
__global__ void assemble_kernel(const float* __restrict__ xlk, const float* __restrict__ xlv,
                                const float* __restrict__ codebook) {
    for (int e = blockIdx.x*blockDim.x + threadIdx.x; e < Bb*Hh*Mm*DKk;
         e += gridDim.x*blockDim.x) {
        int bh  = e >> 16;
        int rem = e & 65535;
        int m = rem >> 7, d = rem & 127;
        size_t dst = ((size_t)bh*WREC + m)*128 + d;
        g_rk[dst] = xlk[e];
        g_rv[dst] = xlv[e];
        int s = g_z[(size_t)bh*Ll + m];
        int h = bh & 7;
        g_rk[((size_t)bh*WREC + Mm + m)*128 + d] = codebook[((size_t)h*Ss + s)*128 + d];
    }
}

// ---------------- 6) fused attention (tiled, smem-staged) --------------------
// grid (L/TQ, H, B), 256 threads
// smem: qu[8][132], qv[8][132], scT[1536][8], tile[64][132], invd[8]
__global__ void __launch_bounds__(256, 2)
attn_kernel(const float* __restrict__ xu, const float* __restrict__ xv,
            const float* __restrict__ xlr, const float* __restrict__ codebook,
            const float* __restrict__ aggU, const float* __restrict__ aggL) {
    extern __shared__ float sm[];
    float* qu   = sm;                    // 8*132
    float* qv   = sm + 8*132;            // 8*132
    float* scT  = sm + 16*132;           // 1536*8 (transposed probs)
    float* tile = scT + 1536*8;          // 64*132
    float* invd = tile + 64*132;         // 8

    int l0 = blockIdx.x * TQ;
    int h  = blockIdx.y;
    int b  = blockIdx.z;
    size_t bh = (size_t)(b*Hh + h);
    int tid = threadIdx.x;

    // load q (+u / +v), vectorized
    {
        int q = tid >> 5, d4 = tid & 31;
        float4 qd = *(const float4*)&g_qn[((bh*Ll + l0 + q) << 7) + d4*4];
        float4 u  = *(const float4*)&xu[h*128 + d4*4];
        float4 vv = *(const float4*)&xv[h*128 + d4*4];
        *(float4*)&qu[q*132 + d4*4] = make_float4(qd.x+u.x,  qd.y+u.y,  qd.z+u.z,  qd.w+u.w);
        *(float4*)&qv[q*132 + d4*4] = make_float4(qd.x+vv.x, qd.y+vv.y, qd.z+vv.z, qd.w+vv.w);
    }
    __syncthreads();

    int w_l = tid & 63, qp = tid >> 6;     // qp in 0..3 -> queries 2qp, 2qp+1
    const float* qa = qu + (2*qp)*132;
    const float* qb = qa + 132;
    const float* qva = qv + (2*qp)*132;
    const float* qvb = qva + 132;

    // ---- AC: qu . recent_k_hat, tiled 16 x 64 keys ----
    for (int wt = 0; wt < 16; wt++) {
        const float* src = g_rk + ((bh*WREC + wt*64) << 7);
        #pragma unroll
        for (int i = 0; i < 8; i++) {
            int f = tid + i*256;
            int r = f >> 5, c4 = f & 31;
            *(float4*)&tile[r*132 + c4*4] = *(const float4*)&src[(r << 7) + c4*4];
        }
        __syncthreads();
        float a0 = 0.f, a1 = 0.f, b0 = 0.f, b1 = 0.f;
        #pragma unroll 8
        for (int d4 = 0; d4 < 32; d4++) {
            float4 k4 = *(float4*)&tile[w_l*132 + d4*4];
            float4 x0 = *(const float4*)&qa[d4*4];
            float4 x1 = *(const float4*)&qb[d4*4];
            a0 += k4.x*x0.x + k4.y*x0.y;  b0 += k4.z*x0.z + k4.w*x0.w;
            a1 += k4.x*x1.x + k4.y*x1.y;  b1 += k4.z*x1.z + k4.w*x1.w;
        }
        int w = wt*64 + w_l;
        scT[w*8 + 2*qp]     = (a0+b0) * INVTAU;
        scT[w*8 + 2*qp + 1] = (a1+b1) * INVTAU;
        __syncthreads();
    }

    // ---- cache: qu . codebook + log(agg_lower), 8 x 64 codes ----
    for (int st = 0; st < 8; st++) {
        const float* src = codebook + (((size_t)h*Ss + st*64) << 7);
        #pragma unroll
        for (int i = 0; i < 8; i++) {
            int f = tid + i*256;
            int r = f >> 5, c4 = f & 31;
            *(float4*)&tile[r*132 + c4*4] = *(const float4*)&src[(r << 7) + c4*4];
        }
        __syncthreads();
        float a0 = 0.f, a1 = 0.f, b0 = 0.f, b1 = 0.f;
        #pragma unroll 8
        for (int d4 = 0; d4 < 32; d4++) {
            float4 k4 = *(float4*)&tile[w_l*132 + d4*4];
            float4 x0 = *(const float4*)&qa[d4*4];
            float4 x1 = *(const float4*)&qb[d4*4];
            a0 += k4.x*x0.x + k4.y*x0.y;  b0 += k4.z*x0.z + k4.w*x0.w;
            a1 += k4.x*x1.x + k4.y*x1.y;  b1 += k4.z*x1.z + k4.w*x1.w;
        }
        int s = st*64 + w_l;
        float al = aggL[bh*Ss + s];
        float bias = (al > 0.f) ? logf(fmaxf(al, 1e-30f)) : -1e30f;
        scT[(1024+s)*8 + 2*qp]     = (a0+b0) * INVTAU + bias;
        scT[(1024+s)*8 + 2*qp + 1] = (a1+b1) * INVTAU + bias;
        __syncthreads();
    }

    // ---- BD: qv . xl_r with rel-shift scatter, 16 x 64 rows ----
    for (int jt = 0; jt < 16; jt++) {
        const float* src = xlr + (((size_t)h*WREC + jt*64) << 7);
        #pragma unroll
        for (int i = 0; i < 8; i++) {
            int f = tid + i*256;
            int r = f >> 5, c4 = f & 31;
            *(float4*)&tile[r*132 + c4*4] = *(const float4*)&src[(r << 7) + c4*4];
        }
        __syncthreads();
        float a0 = 0.f, a1 = 0.f, b0 = 0.f, b1 = 0.f;
        #pragma unroll 8
        for (int d4 = 0; d4 < 32; d4++) {
            float4 k4 = *(float4*)&tile[w_l*132 + d4*4];
            float4 x0 = *(const float4*)&qva[d4*4];
            float4 x1 = *(const float4*)&qvb[d4*4];
            a0 += k4.x*x0.x + k4.y*x0.y;  b0 += k4.z*x0.z + k4.w*x0.w;
            a1 += k4.x*x1.x + k4.y*x1.y;  b1 += k4.z*x1.z + k4.w*x1.w;
        }
        int j = jt*64 + w_l;
        int w0 = j - 511 + l0 + 2*qp;     // w for query 2qp
        if (w0 >= 0 && w0 < 1024)     scT[w0*8 + 2*qp]       += (a0+b0) * INVTAU;
        int w1 = w0 + 1;                  // w for query 2qp+1
        if (w1 >= 0 && w1 < 1024)     scT[w1*8 + 2*qp + 1]   += (a1+b1) * INVTAU;
        __syncthreads();
    }

    // ---- softmax: warp per query over 1536 joint scores ----
    {
        int wq = tid >> 5, lane = tid & 31;
        int limit = l0 + wq + Mm;
        float m = -3.4e38f;
        for (int i = lane; i < 1536; i += 32) {
            float v = scT[i*8 + wq];
            if (i < WREC && i > limit) v = -1e30f;
            m = fmaxf(m, v);
        }
        #pragma unroll
        for (int o = 16; o > 0; o >>= 1) m = fmaxf(m, __shfl_xor_sync(0xffffffffu, m, o));
        float ssum = 0.f;
        for (int i = lane; i < 1536; i += 32) {
            float v = scT[i*8 + wq];
            float p = (i < WREC && i > limit) ? 0.f : __expf(v - m);
            scT[i*8 + wq] = p;
            ssum += p;
        }
        #pragma unroll
        for (int o = 16; o > 0; o >>= 1) ssum += __shfl_xor_sync(0xffffffffu, ssum, o);
        if (lane == 0) invd[wq] = 1.f / ssum;
    }
    __syncthreads();

    // ---- weighted values: thread = (d, half); probs via broadcast LDS128 ----
    int d = tid & 127, half = tid >> 7;
    float acc[TQ];
    #pragma unroll
    for (int q = 0; q < TQ; q++) acc[q] = 0.f;

    if (half == 0) {
        for (int w = 0; w < 768; w++) {
            float vv = g_rv[((bh*WREC + w) << 7) + d];
            float4 p0 = *(float4*)&scT[w*8];
            float4 p1 = *(float4*)&scT[w*8 + 4];
            acc[0] += p0.x*vv; acc[1] += p0.y*vv; acc[2] += p0.z*vv; acc[3] += p0.w*vv;
            acc[4] += p1.x*vv; acc[5] += p1.y*vv; acc[6] += p1.z*vv; acc[7] += p1.w*vv;
        }
    } else {
        for (int w = 768; w < 1024; w++) {
            float vv = g_rv[((bh*WREC + w) << 7) + d];
            float4 p0 = *(float4*)&scT[w*8];
            float4 p1 = *(float4*)&scT[w*8 + 4];
            acc[0] += p0.x*vv; acc[1] += p0.y*vv; acc[2] += p0.z*vv; acc[3] += p0.w*vv;
            acc[4] += p1.x*vv; acc[5] += p1.y*vv; acc[6] += p1.z*vv; acc[7] += p1.w*vv;
        }
        for (int w = 1024; w < 1536; w++) {
            float vv = aggU[((bh*Ss + (w - 1024)) << 7) + d];
            float4 p0 = *(float4*)&scT[w*8];
            float4 p1 = *(float4*)&scT[w*8 + 4];
            acc[0] += p0.x*vv; acc[1] += p0.y*vv; acc[2] += p0.z*vv; acc[3] += p0.w*vv;
            acc[4] += p1.x*vv; acc[5] += p1.y*vv; acc[6] += p1.z*vv; acc[7] += p1.w*vv;
        }
    }
    if (half == 1) {
        #pragma unroll
        for (int q = 0; q < TQ; q++) tile[q*128 + d] = acc[q];
    }
    __syncthreads();
    if (half == 0) {
        #pragma unroll
        for (int q = 0; q < TQ; q++) {
            float tot = (acc[q] + tile[q*128 + d]) * invd[q];
            size_t oi = ((size_t)(b*Ll + l0 + q))*1024 + h*128 + d;
            g_wvg[oi] = tot * g_g[oi];
        }
    }
}

// ---------------- launch ------------------------------------------------------
extern "C" void kernel_launch(void* const* d_in, const int* in_sizes, int n_in,
                              void* d_out, int out_size) {
    const float* input = (const float*)d_in[0];
    const float* xlk   = (const float*)d_in[2];
    const float* xlv   = (const float*)d_in[3];
    const float* aggU  = (const float*)d_in[4];
    const float* aggL  = (const float*)d_in[5];
    const float* Wq    = (const float*)d_in[6];
    const float* Wkvg  = (const float*)d_in[7];
    const float* Wres  = (const float*)d_in[8];
    const float* xu    = (const float*)d_in[9];
    const float* xv    = (const float*)d_in[10];
    const float* xlr   = (const float*)d_in[11];
    const float* cb    = (const float*)d_in[12];
    float* out = (float*)d_out;

    float *xt, *qraw, *kvg, *wvg;
    cudaGetSymbolAddress((void**)&xt,   g_xt);
    cudaGetSymbolAddress((void**)&qraw, g_qraw);
    cudaGetSymbolAddress((void**)&kvg,  g_kvg);
    cudaGetSymbolAddress((void**)&wvg,  g_wvg);

    ln_input_kernel<<<Bb*Ll, 256>>>(input);
    gemm_kernel<<<dim3(1024/128, 4096/128), 256>>>(xt, Wq,   qraw, 4096, 1024, 1024);
    gemm_kernel<<<dim3(3072/128, 4096/128), 256>>>(xt, Wkvg, kvg,  4096, 3072, 1024);
    qkln_kernel<<<dim3(Bb*Ll, Hh), 128>>>();
    vq_kernel<<<dim3(Bb*Hh, Ll/16), 256>>>(cb);
    assemble_kernel<<<4096, 256>>>(xlk, xlv, cb);

    const int attn_smem = (16*132 + 1536*8 + 64*132 + 8) * 4;   // 91424 B
    cudaFuncSetAttribute(attn_kernel, cudaFuncAttributeMaxDynamicSharedMemorySize, attn_smem);
    attn_kernel<<<dim3(Ll/TQ, Hh, Bb), 256, attn_smem>>>(xu, xv, xlr, cb, aggU, aggL);

    gemm_kernel<<<dim3(1024/128, 4096/128), 256>>>(wvg, Wres, out, 4096, 1024, 1024);
}

// round 4
// speedup vs baseline: 2.4031x; 1.1458x over previous
#include <cuda_runtime.h>
#include <math.h>
#include <stdint.h>

// Shapes (fixed for this problem)
#define Bb   8
#define Ll   512
#define Mm   512
#define Hh   8
#define DKk  128
#define DVv  128
#define Ss   512
#define DMm  1024
#define WREC 1024
#define TQ   8

#define INVTAU 0.08838834764831845f   // 1/sqrt(128)

// ---------------- scratch (device globals; no allocation allowed) ------------
__device__ float g_xt  [Bb*Ll*DMm];
__device__ float g_qraw[Bb*Ll*Hh*DKk];
__device__ float g_kvg [Bb*Ll*3072];
__device__ float g_qn  [Bb*Hh*Ll*DKk];
__device__ float g_kn  [Bb*Hh*Ll*DKk];
__device__ float g_g   [Bb*Ll*Hh*DVv];
__device__ float g_rk  [Bb*Hh*WREC*DKk];
__device__ float g_rv  [Bb*Hh*WREC*DVv];
__device__ float g_wvg [Bb*Ll*Hh*DVv];
__device__ int   g_z   [Bb*Hh*Ll];

// ---------------- helpers ----------------------------------------------------
__device__ __forceinline__ float to_tf32(float x) {
    uint32_t u;
    asm("cvt.rna.tf32.f32 %0, %1;" : "=r"(u) : "f"(x));
    return __uint_as_float(u);
}

__device__ __forceinline__ void mma_tf32(float* c, const uint32_t* a, const uint32_t* b) {
    asm volatile(
        "mma.sync.aligned.m16n8k8.row.col.f32.tf32.tf32.f32 "
        "{%0,%1,%2,%3}, {%4,%5,%6,%7}, {%8,%9}, {%0,%1,%2,%3};"
        : "+f"(c[0]), "+f"(c[1]), "+f"(c[2]), "+f"(c[3])
        : "r"(a[0]), "r"(a[1]), "r"(a[2]), "r"(a[3]), "r"(b[0]), "r"(b[1]));
}

__device__ __forceinline__ float blockReduceSum256(float v, float* sh) {
    #pragma unroll
    for (int o = 16; o > 0; o >>= 1) v += __shfl_xor_sync(0xffffffffu, v, o);
    __syncthreads();
    if ((threadIdx.x & 31) == 0) sh[threadIdx.x >> 5] = v;
    __syncthreads();
    float r = 0.f;
    #pragma unroll
    for (int i = 0; i < 8; i++) r += sh[i];
    return r;
}

__device__ __forceinline__ float blockReduceSum128(float v, float* sh) {
    #pragma unroll
    for (int o = 16; o > 0; o >>= 1) v += __shfl_xor_sync(0xffffffffu, v, o);
    __syncthreads();
    if ((threadIdx.x & 31) == 0) sh[threadIdx.x >> 5] = v;
    __syncthreads();
    return sh[0] + sh[1] + sh[2] + sh[3];
}

// ---------------- 1) LayerNorm of input (rows of 1024) -----------------------
__global__ void ln_input_kernel(const float* __restrict__ x) {
    __shared__ float sh[8];
    size_t base = (size_t)blockIdx.x * DMm;
    float lv[4]; float s = 0.f;
    #pragma unroll
    for (int j = 0; j < 4; j++) { lv[j] = x[base + threadIdx.x + j*256]; s += lv[j]; }
    float mu = blockReduceSum256(s, sh) * (1.f/1024.f);
    float s2 = 0.f;
    #pragma unroll
    for (int j = 0; j < 4; j++) { float d = lv[j] - mu; s2 += d*d; }
    float var = blockReduceSum256(s2, sh) * (1.f/1024.f);
    float rstd = rsqrtf(var + 1e-6f);
    #pragma unroll
    for (int j = 0; j < 4; j++) g_xt[base + threadIdx.x + j*256] = (lv[j]-mu)*rstd;
}

// ---------------- 2a) fp32 FFMA GEMM (full precision, for k-columns) ---------
// 128x128 tile, BK=16, 256 threads, 8x8 microtile. N is the ld of B and C;
// columns covered = blockIdx.x*128 .. +128.
__global__ void __launch_bounds__(256, 2)
gemm_ffma_kernel(const float* __restrict__ A, const float* __restrict__ B,
                 float* __restrict__ C, int M, int N, int K) {
    __shared__ float As[16][132];   // [k][m]
    __shared__ float Bs[16][132];   // [k][n]
    int tid  = threadIdx.x;
    int row0 = blockIdx.y * 128;
    int col0 = blockIdx.x * 128;
    int tx = tid & 15, ty = tid >> 4;

    float acc[8][8];
    #pragma unroll
    for (int i = 0; i < 8; i++)
        #pragma unroll
        for (int j = 0; j < 8; j++) acc[i][j] = 0.f;

    for (int k0 = 0; k0 < K; k0 += 16) {
        #pragma unroll
        for (int i = 0; i < 2; i++) {
            int f = tid + i*256;
            int r = f >> 2, c4 = f & 3;
            float4 v = *(const float4*)&A[(size_t)(row0 + r)*K + k0 + c4*4];
            As[c4*4+0][r] = v.x; As[c4*4+1][r] = v.y;
            As[c4*4+2][r] = v.z; As[c4*4+3][r] = v.w;
        }
        #pragma unroll
        for (int i = 0; i < 2; i++) {
            int f = tid + i*256;
            int r = f >> 5, c4 = f & 31;
            *(float4*)&Bs[r][c4*4] = *(const float4*)&B[(size_t)(k0 + r)*N + col0 + c4*4];
        }
        __syncthreads();
        #pragma unroll
        for (int kk = 0; kk < 16; kk++) {
            float a[8], bb[8];
            *(float4*)&a[0]  = *(float4*)&As[kk][ty*8];
            *(float4*)&a[4]  = *(float4*)&As[kk][ty*8 + 4];
            *(float4*)&bb[0] = *(float4*)&Bs[kk][tx*4];
            *(float4*)&bb[4] = *(float4*)&Bs[kk][64 + tx*4];
            #pragma unroll
            for (int i = 0; i < 8; i++)
                #pragma unroll
                for (int j = 0; j < 8; j++) acc[i][j] += a[i]*bb[j];
        }
        __syncthreads();
    }
    #pragma unroll
    for (int i = 0; i < 8; i++) {
        size_t crow = (size_t)(row0 + ty*8 + i)*N;
        *(float4*)&C[crow + col0 + tx*4]      = make_float4(acc[i][0], acc[i][1], acc[i][2], acc[i][3]);
        *(float4*)&C[crow + col0 + 64 + tx*4] = make_float4(acc[i][4], acc[i][5], acc[i][6], acc[i][7]);
    }
}

// ---------------- 2b) tf32 tensor-core GEMM (continuous paths) ---------------
// 128x128 tile, BK=32, 256 threads = 8 warps in 4(m) x 2(n); warp tile 32x64.
__global__ void __launch_bounds__(256, 2)
gemm_tf32_kernel(const float* __restrict__ A, const float* __restrict__ B,
                 float* __restrict__ C, int M, int N, int K) {
    __shared__ float As[128][36];
    __shared__ float Bs[32][132];
    int tid  = threadIdx.x;
    int warp = tid >> 5, lane = tid & 31;
    int g  = lane >> 2, tg = lane & 3;
    int wm = (warp >> 1) * 32;
    int wn = (warp & 1) * 64;
    int row0 = blockIdx.y * 128;
    int col0 = blockIdx.x * 128;

    float c[2][8][4];
    #pragma unroll
    for (int mt = 0; mt < 2; mt++)
        #pragma unroll
        for (int nt = 0; nt < 8; nt++)
            #pragma unroll
            for (int j = 0; j < 4; j++) c[mt][nt][j] = 0.f;

    for (int k0 = 0; k0 < K; k0 += 32) {
        #pragma unroll
        for (int i = 0; i < 4; i++) {
            int f = tid + i*256;
            int r = f >> 3, cc = (f & 7) * 4;
            float4 v = *(const float4*)&A[(size_t)(row0 + r)*K + k0 + cc];
            As[r][cc+0] = to_tf32(v.x); As[r][cc+1] = to_tf32(v.y);
            As[r][cc+2] = to_tf32(v.z); As[r][cc+3] = to_tf32(v.w);
        }
        #pragma unroll
        for (int i = 0; i < 4; i++) {
            int f = tid + i*256;
            int r = f >> 5, cc = (f & 31) * 4;
            float4 v = *(const float4*)&B[(size_t)(k0 + r)*N + col0 + cc];
            Bs[r][cc+0] = to_tf32(v.x); Bs[r][cc+1] = to_tf32(v.y);
            Bs[r][cc+2] = to_tf32(v.z); Bs[r][cc+3] = to_tf32(v.w);
        }
        __syncthreads();
        #pragma unroll
        for (int ks = 0; ks < 4; ks++) {
            int kk = ks * 8;
            uint32_t a[2][4], b[8][2];
            #pragma unroll
            for (int mt = 0; mt < 2; mt++) {
                int m0 = wm + mt*16;
                a[mt][0] = __float_as_uint(As[m0 + g    ][kk + tg    ]);
                a[mt][1] = __float_as_uint(As[m0 + g + 8][kk + tg    ]);
                a[mt][2] = __float_as_uint(As[m0 + g    ][kk + tg + 4]);
                a[mt][3] = __float_as_uint(As[m0 + g + 8][kk + tg + 4]);
            }
            #pragma unroll
            for (int nt = 0; nt < 8; nt++) {
                int n0 = wn + nt*8 + g;
                b[nt][0] = __float_as_uint(Bs[kk + tg    ][n0]);
                b[nt][1] = __float_as_uint(Bs[kk + tg + 4][n0]);
            }
            #pragma unroll
            for (int mt = 0; mt < 2; mt++)
                #pragma unroll
                for (int nt = 0; nt < 8; nt++)
                    mma_tf32(c[mt][nt], a[mt], b[nt]);
        }
        __syncthreads();
    }

    #pragma unroll
    for (int mt = 0; mt < 2; mt++) {
        int row = row0 + wm + mt*16 + g;
        #pragma unroll
        for (int nt = 0; nt < 8; nt++) {
            int col = col0 + wn + nt*8 + tg*2;
            *(float2*)&C[(size_t)row*N + col]     = make_float2(c[mt][nt][0], c[mt][nt][1]);
            *(float2*)&C[(size_t)(row+8)*N + col] = make_float2(c[mt][nt][2], c[mt][nt][3]);
        }
    }
}

// ---------------- 3) per-head LN of q and k, v copy, gate --------------------
__global__ void qkln_kernel() {
    __shared__ float sh[4];
    int bl = blockIdx.x, h = blockIdx.y, t = threadIdx.x;
    int b = bl >> 9, l = bl & 511;
    size_t bh = (size_t)(b*Hh + h);

    float x  = g_qraw[(size_t)bl*1024 + h*128 + t];
    float mu = blockReduceSum128(x, sh) * (1.f/128.f);
    float d  = x - mu;
    float var = blockReduceSum128(d*d, sh) * (1.f/128.f);
    g_qn[(bh*Ll + l)*128 + t] = d * rsqrtf(var + 1e-6f);

    x  = g_kvg[(size_t)bl*3072 + h*128 + t];
    mu = blockReduceSum128(x, sh) * (1.f/128.f);
    d  = x - mu;
    var = blockReduceSum128(d*d, sh) * (1.f/128.f);
    g_kn[(bh*Ll + l)*128 + t] = d * rsqrtf(var + 1e-6f);

    g_rv[(bh*WREC + Mm + l)*128 + t] = g_kvg[(size_t)bl*3072 + 1024 + h*128 + t];

    float gx = g_kvg[(size_t)bl*3072 + 2048 + h*128 + t];
    g_g[(size_t)bl*1024 + h*128 + t] = gx / (1.f + __expf(-gx));
}

// ---------------- 4) VQ argmin over 512 codes (float4 codebook reads) --------
__global__ void vq_kernel(const float* __restrict__ codebook) {
    __shared__ float ks[16][128];
    __shared__ float redv[16][256];
    __shared__ int   redi[16][256];
    int bh = blockIdx.x, lt = blockIdx.y;
    int h  = bh & 7;
    int tid = threadIdx.x;
    #pragma unroll
    for (int j = 0; j < 2; j++) {
        int f = tid + j*256;
        int r = f >> 5, c4 = f & 31;
        *(float4*)&ks[r][c4*4] =
            *(const float4*)&g_kn[((size_t)bh*Ll + lt*16 + r)*128 + c4*4];
    }
    __syncthreads();

    float best[16]; int bidx[16];
    #pragma unroll
    for (int r = 0; r < 16; r++) { best[r] = 3.4e38f; bidx[r] = 0; }

    for (int s = tid; s < Ss; s += 256) {
        const float4* c = (const float4*)(codebook + ((size_t)h*Ss + s)*128);
        float cc = 0.f; float acc[16];
        #pragma unroll
        for (int r = 0; r < 16; r++) acc[r] = 0.f;
        #pragma unroll 4
        for (int d4 = 0; d4 < 32; d4++) {
            float4 cv = c[d4];
            cc += cv.x*cv.x + cv.y*cv.y + cv.z*cv.z + cv.w*cv.w;
            #pragma unroll
            for (int r = 0; r < 16; r++) {
                float4 kv = *(float4*)&ks[r][d4*4];
                acc[r] += cv.x*kv.x + cv.y*kv.y + cv.z*kv.z + cv.w*kv.w;
            }
        }
        #pragma unroll
        for (int r = 0; r < 16; r++) {
            float d2 = cc - 2.f*acc[r];
            if (d2 < best[r]) { best[r] = d2; bidx[r] = s; }
        }
    }
    #pragma unroll
    for (int r = 0; r < 16; r++) { redv[r][tid] = best[r]; redi[r][tid] = bidx[r]; }
    __syncthreads();

    int warp = tid >> 5, lane = tid & 31;
    for (int r = warp*2; r < warp*2 + 2; r++) {
        float bv = 3.4e38f; int bi = 0x7fffffff;
        for (int t = lane; t < 256; t += 32) {
            float v = redv[r][t]; int i = redi[r][t];
            if (v < bv || (v == bv && i < bi)) { bv = v; bi = i; }
        }
        #pragma unroll
        for (int o = 16; o > 0; o >>= 1) {
            float ov = __shfl_xor_sync(0xffffffffu, bv, o);
            int   oi = __shfl_xor_sync(0xffffffffu, bi, o);
            if (ov < bv || (ov == bv && oi < bi)) { bv = ov; bi = oi; }
        }
        if (lane == 0) g_z[(size_t)bh*Ll + lt*16 + r] = bi;
    }
}

// ---------------- 5) assemble recent buffers ---------------------------------
__global__ void assemble_kernel(const float* __restrict__ xlk, const float* __restrict__ xlv,
                                const float* __restrict__ codebook) {
    for (int e = blockIdx.x*blockDim.x + threadIdx.x; e < Bb*Hh*Mm*DKk;
         e += gridDim.x*blockDim.x) {
        int bh  = e >> 16;
        int rem = e & 65535;
        int m = rem >> 7, d = rem & 127;
        size_t dst = ((size_t)bh*WREC + m)*128 + d;
        g_rk[dst] = xlk[e];
        g_rv[dst] = xlv[e];
        int s = g_z[(size_t)bh*Ll + m];
        int h = bh & 7;
        g_rk[((size_t)bh*WREC + Mm + m)*128 + d] = codebook[((size_t)h*Ss + s)*128 + d];
    }
}

// ---------------- 6) fused attention (tiled, smem-staged) --------------------
__global__ void __launch_bounds__(256, 2)
attn_kernel(const float* __restrict__ xu, const float* __restrict__ xv,
            const float* __restrict__ xlr, const float* __restrict__ codebook,
            const float* __restrict__ aggU, const float* __restrict__ aggL) {
    extern __shared__ float sm[];
    float* qu   = sm;                    // 8*132
    float* qv   = sm + 8*132;            // 8*132
    float* scT  = sm + 16*132;           // 1536*8 (transposed probs)
    float* tile = scT + 1536*8;          // 64*132
    float* invd = tile + 64*132;         // 8

    int l0 = blockIdx.x * TQ;
    int h  = blockIdx.y;
    int b  = blockIdx.z;
    size_t bh = (size_t)(b*Hh + h);
    int tid = threadIdx.x;

    {
        int q = tid >> 5, d4 = tid & 31;
        float4 qd = *(const float4*)&g_qn[((bh*Ll + l0 + q) << 7) + d4*4];
        float4 u  = *(const float4*)&xu[h*128 + d4*4];
        float4 vv = *(const float4*)&xv[h*128 + d4*4];
        *(float4*)&qu[q*132 + d4*4] = make_float4(qd.x+u.x,  qd.y+u.y,  qd.z+u.z,  qd.w+u.w);
        *(float4*)&qv[q*132 + d4*4] = make_float4(qd.x+vv.x, qd.y+vv.y, qd.z+vv.z, qd.w+vv.w);
    }
    __syncthreads();

    int w_l = tid & 63, qp = tid >> 6;
    const float* qa  = qu + (2*qp)*132;
    const float* qb  = qa + 132;
    const float* qva = qv + (2*qp)*132;
    const float* qvb = qva + 132;

    // ---- AC: qu . recent_k_hat, tiled 16 x 64 keys ----
    for (int wt = 0; wt < 16; wt++) {
        const float* src = g_rk + ((bh*WREC + wt*64) << 7);
        #pragma unroll
        for (int i = 0; i < 8; i++) {
            int f = tid + i*256;
            int r = f >> 5, c4 = f & 31;
            *(float4*)&tile[r*132 + c4*4] = *(const float4*)&src[(r << 7) + c4*4];
        }
        __syncthreads();
        float a0 = 0.f, a1 = 0.f, b0 = 0.f, b1 = 0.f;
        #pragma unroll 8
        for (int d4 = 0; d4 < 32; d4++) {
            float4 k4 = *(float4*)&tile[w_l*132 + d4*4];
            float4 x0 = *(const float4*)&qa[d4*4];
            float4 x1 = *(const float4*)&qb[d4*4];
            a0 += k4.x*x0.x + k4.y*x0.y;  b0 += k4.z*x0.z + k4.w*x0.w;
            a1 += k4.x*x1.x + k4.y*x1.y;  b1 += k4.z*x1.z + k4.w*x1.w;
        }
        int w = wt*64 + w_l;
        scT[w*8 + 2*qp]     = (a0+b0) * INVTAU;
        scT[w*8 + 2*qp + 1] = (a1+b1) * INVTAU;
        __syncthreads();
    }

    // ---- cache: qu . codebook + log(agg_lower) ----
    for (int st = 0; st < 8; st++) {
        const float* src = codebook + (((size_t)h*Ss + st*64) << 7);
        #pragma unroll
        for (int i = 0; i < 8; i++) {
            int f = tid + i*256;
            int r = f >> 5, c4 = f & 31;
            *(float4*)&tile[r*132 + c4*4] = *(const float4*)&src[(r << 7) + c4*4];
        }
        __syncthreads();
        float a0 = 0.f, a1 = 0.f, b0 = 0.f, b1 = 0.f;
        #pragma unroll 8
        for (int d4 = 0; d4 < 32; d4++) {
            float4 k4 = *(float4*)&tile[w_l*132 + d4*4];
            float4 x0 = *(const float4*)&qa[d4*4];
            float4 x1 = *(const float4*)&qb[d4*4];
            a0 += k4.x*x0.x + k4.y*x0.y;  b0 += k4.z*x0.z + k4.w*x0.w;
            a1 += k4.x*x1.x + k4.y*x1.y;  b1 += k4.z*x1.z + k4.w*x1.w;
        }
        int s = st*64 + w_l;
        float al = aggL[bh*Ss + s];
        float bias = (al > 0.f) ? logf(fmaxf(al, 1e-30f)) : -1e30f;
        scT[(1024+s)*8 + 2*qp]     = (a0+b0) * INVTAU + bias;
        scT[(1024+s)*8 + 2*qp + 1] = (a1+b1) * INVTAU + bias;
        __syncthreads();
    }

    // ---- BD: qv . xl_r with rel-shift scatter ----
    for (int jt = 0; jt < 16; jt++) {
        const float* src = xlr + (((size_t)h*WREC + jt*64) << 7);
        #pragma unroll
        for (int i = 0; i < 8; i++) {
            int f = tid + i*256;
            int r = f >> 5, c4 = f & 31;
            *(float4*)&tile[r*132 + c4*4] = *(const float4*)&src[(r << 7) + c4*4];
        }
        __syncthreads();
        float a0 = 0.f, a1 = 0.f, b0 = 0.f, b1 = 0.f;
        #pragma unroll 8
        for (int d4 = 0; d4 < 32; d4++) {
            float4 k4 = *(float4*)&tile[w_l*132 + d4*4];
            float4 x0 = *(const float4*)&qva[d4*4];
            float4 x1 = *(const float4*)&qvb[d4*4];
            a0 += k4.x*x0.x + k4.y*x0.y;  b0 += k4.z*x0.z + k4.w*x0.w;
            a1 += k4.x*x1.x + k4.y*x1.y;  b1 += k4.z*x1.z + k4.w*x1.w;
        }
        int j = jt*64 + w_l;
        int w0 = j - 511 + l0 + 2*qp;
        if (w0 >= 0 && w0 < 1024)  scT[w0*8 + 2*qp]     += (a0+b0) * INVTAU;
        int w1 = w0 + 1;
        if (w1 >= 0 && w1 < 1024)  scT[w1*8 + 2*qp + 1] += (a1+b1) * INVTAU;
        __syncthreads();
    }

    // ---- softmax: warp per query over 1536 joint scores ----
    {
        int wq = tid >> 5, lane = tid & 31;
        int limit = l0 + wq + Mm;
        float m = -3.4e38f;
        for (int i = lane; i < 1536; i += 32) {
            float v = scT[i*8 + wq];
            if (i < WREC && i > limit) v = -1e30f;
            m = fmaxf(m, v);
        }
        #pragma unroll
        for (int o = 16; o > 0; o >>= 1) m = fmaxf(m, __shfl_xor_sync(0xffffffffu, m, o));
        float ssum = 0.f;
        for (int i = lane; i < 1536; i += 32) {
            float v = scT[i*8 + wq];
            float p = (i < WREC && i > limit) ? 0.f : __expf(v - m);
            scT[i*8 + wq] = p;
            ssum += p;
        }
        #pragma unroll
        for (int o = 16; o > 0; o >>= 1) ssum += __shfl_xor_sync(0xffffffffu, ssum, o);
        if (lane == 0) invd[wq] = 1.f / ssum;
    }
    __syncthreads();

    // ---- weighted values ----
    int d = tid & 127, half = tid >> 7;
    float acc[TQ];
    #pragma unroll
    for (int q = 0; q < TQ; q++) acc[q] = 0.f;

    if (half == 0) {
        for (int w = 0; w < 768; w++) {
            float vv = g_rv[((bh*WREC + w) << 7) + d];
            float4 p0 = *(float4*)&scT[w*8];
            float4 p1 = *(float4*)&scT[w*8 + 4];
            acc[0] += p0.x*vv; acc[1] += p0.y*vv; acc[2] += p0.z*vv; acc[3] += p0.w*vv;
            acc[4] += p1.x*vv; acc[5] += p1.y*vv; acc[6] += p1.z*vv; acc[7] += p1.w*vv;
        }
    } else {
        for (int w = 768; w < 1024; w++) {
            float vv = g_rv[((bh*WREC + w) << 7) + d];
            float4 p0 = *(float4*)&scT[w*8];
            float4 p1 = *(float4*)&scT[w*8 + 4];
            acc[0] += p0.x*vv; acc[1] += p0.y*vv; acc[2] += p0.z*vv; acc[3] += p0.w*vv;
            acc[4] += p1.x*vv; acc[5] += p1.y*vv; acc[6] += p1.z*vv; acc[7] += p1.w*vv;
        }
        for (int w = 1024; w < 1536; w++) {
            float vv = aggU[((bh*Ss + (w - 1024)) << 7) + d];
            float4 p0 = *(float4*)&scT[w*8];
            float4 p1 = *(float4*)&scT[w*8 + 4];
            acc[0] += p0.x*vv; acc[1] += p0.y*vv; acc[2] += p0.z*vv; acc[3] += p0.w*vv;
            acc[4] += p1.x*vv; acc[5] += p1.y*vv; acc[6] += p1.z*vv; acc[7] += p1.w*vv;
        }
    }
    if (half == 1) {
        #pragma unroll
        for (int q = 0; q < TQ; q++) tile[q*128 + d] = acc[q];
    }
    __syncthreads();
    if (half == 0) {
        #pragma unroll
        for (int q = 0; q < TQ; q++) {
            float tot = (acc[q] + tile[q*128 + d]) * invd[q];
            size_t oi = ((size_t)(b*Ll + l0 + q))*1024 + h*128 + d;
            g_wvg[oi] = tot * g_g[oi];
        }
    }
}

// ---------------- launch ------------------------------------------------------
extern "C" void kernel_launch(void* const* d_in, const int* in_sizes, int n_in,
                              void* d_out, int out_size) {
    const float* input = (const float*)d_in[0];
    const float* xlk   = (const float*)d_in[2];
    const float* xlv   = (const float*)d_in[3];
    const float* aggU  = (const float*)d_in[4];
    const float* aggL  = (const float*)d_in[5];
    const float* Wq    = (const float*)d_in[6];
    const float* Wkvg  = (const float*)d_in[7];
    const float* Wres  = (const float*)d_in[8];
    const float* xu    = (const float*)d_in[9];
    const float* xv    = (const float*)d_in[10];
    const float* xlr   = (const float*)d_in[11];
    const float* cb    = (const float*)d_in[12];
    float* out = (float*)d_out;

    float *xt, *qraw, *kvg, *wvg;
    cudaGetSymbolAddress((void**)&xt,   g_xt);
    cudaGetSymbolAddress((void**)&qraw, g_qraw);
    cudaGetSymbolAddress((void**)&kvg,  g_kvg);
    cudaGetSymbolAddress((void**)&wvg,  g_wvg);

    ln_input_kernel<<<Bb*Ll, 256>>>(input);
    // q projection: tf32 (continuous consumer)
    gemm_tf32_kernel<<<dim3(1024/128, 4096/128), 256>>>(xt, Wq, qraw, 4096, 1024, 1024);
    // kvg: k columns (0..1023) in full fp32 (feeds VQ argmin — discrete);
    //      v,g columns (1024..3071) in tf32
    gemm_ffma_kernel<<<dim3(1024/128, 4096/128), 256>>>(xt, Wkvg, kvg, 4096, 3072, 1024);
    gemm_tf32_kernel<<<dim3(2048/128, 4096/128), 256>>>(xt, Wkvg + 1024, kvg + 1024,
                                                        4096, 3072, 1024);
    qkln_kernel<<<dim3(Bb*Ll, Hh), 128>>>();
    vq_kernel<<<dim3(Bb*Hh, Ll/16), 256>>>(cb);
    assemble_kernel<<<4096, 256>>>(xlk, xlv, cb);

    const int attn_smem = (16*132 + 1536*8 + 64*132 + 8) * 4;   // 91424 B
    cudaFuncSetAttribute(attn_kernel, cudaFuncAttributeMaxDynamicSharedMemorySize, attn_smem);
    attn_kernel<<<dim3(Ll/TQ, Hh, Bb), 256, attn_smem>>>(xu, xv, xlr, cb, aggU, aggL);

    gemm_tf32_kernel<<<dim3(1024/128, 4096/128), 256>>>(wvg, Wres, out, 4096, 1024, 1024);
}

// round 5
// speedup vs baseline: 5.1126x; 2.1275x over previous
#include <cuda_runtime.h>
#include <math.h>
#include <stdint.h>

// Shapes (fixed for this problem)
#define Bb   8
#define Ll   512
#define Mm   512
#define Hh   8
#define DKk  128
#define DVv  128
#define Ss   512
#define DMm  1024
#define WREC 1024
#define WTOT 1536    // recent 1024 + cache 512

#define INVTAU 0.08838834764831845f   // 1/sqrt(128)

// ---------------- scratch (device globals; no allocation allowed) ------------
__device__ float g_xt  [Bb*Ll*DMm];
__device__ float g_qraw[Bb*Ll*Hh*DKk];
__device__ float g_kvg [Bb*Ll*3072];
__device__ float g_kn  [Bb*Hh*Ll*DKk];
__device__ float g_g   [Bb*Ll*Hh*DVv];
__device__ float g_qu  [64*Ll*DKk];          // q + x_u  (b,h,l,d)
__device__ float g_qv  [64*Ll*DKk];          // q + x_v
__device__ float g_keys[64*WTOT*DKk];        // [xl_k_hat; c_z gather; codebook]
__device__ float g_vals[64*WTOT*DVv];        // [xl_v; v; agg_upper]
__device__ float g_S1  [(size_t)64*Ll*WTOT]; // scores -> probs (201 MB)
__device__ float g_S2  [(size_t)64*Ll*WREC]; // BD term (134 MB)
__device__ float g_wvg [Bb*Ll*Hh*DVv];
__device__ int   g_z   [Bb*Hh*Ll];

// ---------------- helpers ----------------------------------------------------
__device__ __forceinline__ float to_tf32(float x) {
    uint32_t u;
    asm("cvt.rna.tf32.f32 %0, %1;" : "=r"(u) : "f"(x));
    return __uint_as_float(u);
}

__device__ __forceinline__ void mma_tf32(float* c, const uint32_t* a, const uint32_t* b) {
    asm volatile(
        "mma.sync.aligned.m16n8k8.row.col.f32.tf32.tf32.f32 "
        "{%0,%1,%2,%3}, {%4,%5,%6,%7}, {%8,%9}, {%0,%1,%2,%3};"
        : "+f"(c[0]), "+f"(c[1]), "+f"(c[2]), "+f"(c[3])
        : "r"(a[0]), "r"(a[1]), "r"(a[2]), "r"(a[3]), "r"(b[0]), "r"(b[1]));
}

__device__ __forceinline__ float blockReduceSum256(float v, float* sh) {
    #pragma unroll
    for (int o = 16; o > 0; o >>= 1) v += __shfl_xor_sync(0xffffffffu, v, o);
    __syncthreads();
    if ((threadIdx.x & 31) == 0) sh[threadIdx.x >> 5] = v;
    __syncthreads();
    float r = 0.f;
    #pragma unroll
    for (int i = 0; i < 8; i++) r += sh[i];
    return r;
}

__device__ __forceinline__ float blockReduceSum128(float v, float* sh) {
    #pragma unroll
    for (int o = 16; o > 0; o >>= 1) v += __shfl_xor_sync(0xffffffffu, v, o);
    __syncthreads();
    if ((threadIdx.x & 31) == 0) sh[threadIdx.x >> 5] = v;
    __syncthreads();
    return sh[0] + sh[1] + sh[2] + sh[3];
}

// ---------------- 1) LayerNorm of input (rows of 1024) -----------------------
__global__ void ln_input_kernel(const float* __restrict__ x) {
    __shared__ float sh[8];
    size_t base = (size_t)blockIdx.x * DMm;
    float lv[4]; float s = 0.f;
    #pragma unroll
    for (int j = 0; j < 4; j++) { lv[j] = x[base + threadIdx.x + j*256]; s += lv[j]; }
    float mu = blockReduceSum256(s, sh) * (1.f/1024.f);
    float s2 = 0.f;
    #pragma unroll
    for (int j = 0; j < 4; j++) { float d = lv[j] - mu; s2 += d*d; }
    float var = blockReduceSum256(s2, sh) * (1.f/1024.f);
    float rstd = rsqrtf(var + 1e-6f);
    #pragma unroll
    for (int j = 0; j < 4; j++) g_xt[base + threadIdx.x + j*256] = (lv[j]-mu)*rstd;
}

// ---------------- 2a) fp32 FFMA GEMM (full precision, k-columns) -------------
__global__ void __launch_bounds__(256, 2)
gemm_ffma_kernel(const float* __restrict__ A, const float* __restrict__ B,
                 float* __restrict__ C, int M, int N, int K) {
    __shared__ float As[16][132];
    __shared__ float Bs[16][132];
    int tid  = threadIdx.x;
    int row0 = blockIdx.y * 128;
    int col0 = blockIdx.x * 128;
    int tx = tid & 15, ty = tid >> 4;

    float acc[8][8];
    #pragma unroll
    for (int i = 0; i < 8; i++)
        #pragma unroll
        for (int j = 0; j < 8; j++) acc[i][j] = 0.f;

    for (int k0 = 0; k0 < K; k0 += 16) {
        #pragma unroll
        for (int i = 0; i < 2; i++) {
            int f = tid + i*256;
            int r = f >> 2, c4 = f & 3;
            float4 v = *(const float4*)&A[(size_t)(row0 + r)*K + k0 + c4*4];
            As[c4*4+0][r] = v.x; As[c4*4+1][r] = v.y;
            As[c4*4+2][r] = v.z; As[c4*4+3][r] = v.w;
        }
        #pragma unroll
        for (int i = 0; i < 2; i++) {
            int f = tid + i*256;
            int r = f >> 5, c4 = f & 31;
            *(float4*)&Bs[r][c4*4] = *(const float4*)&B[(size_t)(k0 + r)*N + col0 + c4*4];
        }
        __syncthreads();
        #pragma unroll
        for (int kk = 0; kk < 16; kk++) {
            float a[8], bb[8];
            *(float4*)&a[0]  = *(float4*)&As[kk][ty*8];
            *(float4*)&a[4]  = *(float4*)&As[kk][ty*8 + 4];
            *(float4*)&bb[0] = *(float4*)&Bs[kk][tx*4];
            *(float4*)&bb[4] = *(float4*)&Bs[kk][64 + tx*4];
            #pragma unroll
            for (int i = 0; i < 8; i++)
                #pragma unroll
                for (int j = 0; j < 8; j++) acc[i][j] += a[i]*bb[j];
        }
        __syncthreads();
    }
    #pragma unroll
    for (int i = 0; i < 8; i++) {
        size_t crow = (size_t)(row0 + ty*8 + i)*N;
        *(float4*)&C[crow + col0 + tx*4]      = make_float4(acc[i][0], acc[i][1], acc[i][2], acc[i][3]);
        *(float4*)&C[crow + col0 + 64 + tx*4] = make_float4(acc[i][4], acc[i][5], acc[i][6], acc[i][7]);
    }
}

// ---------------- 2b) tf32 tensor-core GEMM (continuous projections) ---------
__global__ void __launch_bounds__(256, 2)
gemm_tf32_kernel(const float* __restrict__ A, const float* __restrict__ B,
                 float* __restrict__ C, int M, int N, int K) {
    __shared__ float As[128][36];
    __shared__ float Bs[32][132];
    int tid  = threadIdx.x;
    int warp = tid >> 5, lane = tid & 31;
    int g  = lane >> 2, tg = lane & 3;
    int wm = (warp >> 1) * 32;
    int wn = (warp & 1) * 64;
    int row0 = blockIdx.y * 128;
    int col0 = blockIdx.x * 128;

    float c[2][8][4];
    #pragma unroll
    for (int mt = 0; mt < 2; mt++)
        #pragma unroll
        for (int nt = 0; nt < 8; nt++)
            #pragma unroll
            for (int j = 0; j < 4; j++) c[mt][nt][j] = 0.f;

    for (int k0 = 0; k0 < K; k0 += 32) {
        #pragma unroll
        for (int i = 0; i < 4; i++) {
            int f = tid + i*256;
            int r = f >> 3, cc = (f & 7) * 4;
            float4 v = *(const float4*)&A[(size_t)(row0 + r)*K + k0 + cc];
            As[r][cc+0] = to_tf32(v.x); As[r][cc+1] = to_tf32(v.y);
            As[r][cc+2] = to_tf32(v.z); As[r][cc+3] = to_tf32(v.w);
        }
        #pragma unroll
        for (int i = 0; i < 4; i++) {
            int f = tid + i*256;
            int r = f >> 5, cc = (f & 31) * 4;
            float4 v = *(const float4*)&B[(size_t)(k0 + r)*N + col0 + cc];
            Bs[r][cc+0] = to_tf32(v.x); Bs[r][cc+1] = to_tf32(v.y);
            Bs[r][cc+2] = to_tf32(v.z); Bs[r][cc+3] = to_tf32(v.w);
        }
        __syncthreads();
        #pragma unroll
        for (int ks = 0; ks < 4; ks++) {
            int kk = ks * 8;
            uint32_t a[2][4], b[8][2];
            #pragma unroll
            for (int mt = 0; mt < 2; mt++) {
                int m0 = wm + mt*16;
                a[mt][0] = __float_as_uint(As[m0 + g    ][kk + tg    ]);
                a[mt][1] = __float_as_uint(As[m0 + g + 8][kk + tg    ]);
                a[mt][2] = __float_as_uint(As[m0 + g    ][kk + tg + 4]);
                a[mt][3] = __float_as_uint(As[m0 + g + 8][kk + tg + 4]);
            }
            #pragma unroll
            for (int nt = 0; nt < 8; nt++) {
                int n0 = wn + nt*8 + g;
                b[nt][0] = __float_as_uint(Bs[kk + tg    ][n0]);
                b[nt][1] = __float_as_uint(Bs[kk + tg + 4][n0]);
            }
            #pragma unroll
            for (int mt = 0; mt < 2; mt++)
                #pragma unroll
                for (int nt = 0; nt < 8; nt++)
                    mma_tf32(c[mt][nt], a[mt], b[nt]);
        }
        __syncthreads();
    }

    #pragma unroll
    for (int mt = 0; mt < 2; mt++) {
        int row = row0 + wm + mt*16 + g;
        #pragma unroll
        for (int nt = 0; nt < 8; nt++) {
            int col = col0 + wn + nt*8 + tg*2;
            *(float2*)&C[(size_t)row*N + col]     = make_float2(c[mt][nt][0], c[mt][nt][1]);
            *(float2*)&C[(size_t)(row+8)*N + col] = make_float2(c[mt][nt][2], c[mt][nt][3]);
        }
    }
}

// ---------------- 2c) batched NT 3xTF32 GEMM: C[z] = A[z] @ B[z]^T -----------
// A: [M][K] row-major (K=128), B: [N][K] row-major, C: [M][N].
// bPerHead: B offset stride uses (z&7) instead of z.
__global__ void __launch_bounds__(256, 2)
gemm_nt3x_kernel(const float* __restrict__ A, const float* __restrict__ B,
                 float* __restrict__ C, int N,
                 size_t strideA, size_t strideB, size_t strideC, int bPerHead) {
    extern __shared__ float sm[];
    float (*Ah)[36] = (float(*)[36])sm;
    float (*Al)[36] = (float(*)[36])(sm + 128*36);
    float (*Bh)[36] = (float(*)[36])(sm + 2*128*36);
    float (*Bl)[36] = (float(*)[36])(sm + 3*128*36);

    int z = blockIdx.z;
    const float* Az = A + (size_t)z * strideA;
    const float* Bz = B + (size_t)(bPerHead ? (z & 7) : z) * strideB;
    float* Cz = C + (size_t)z * strideC;

    int tid  = threadIdx.x;
    int warp = tid >> 5, lane = tid & 31;
    int g  = lane >> 2, tg = lane & 3;
    int wm = (warp >> 1) * 32;
    int wn = (warp & 1) * 64;
    int row0 = blockIdx.y * 128;
    int col0 = blockIdx.x * 128;

    float c[2][8][4];
    #pragma unroll
    for (int mt = 0; mt < 2; mt++)
        #pragma unroll
        for (int nt = 0; nt < 8; nt++)
            #pragma unroll
            for (int j = 0; j < 4; j++) c[mt][nt][j] = 0.f;

    for (int k0 = 0; k0 < 128; k0 += 32) {
        #pragma unroll
        for (int i = 0; i < 4; i++) {
            int f = tid + i*256;
            int r = f >> 3, cc = (f & 7) * 4;
            float4 v = *(const float4*)&Az[(size_t)(row0 + r)*128 + k0 + cc];
            float hx = to_tf32(v.x), hy = to_tf32(v.y), hz = to_tf32(v.z), hw = to_tf32(v.w);
            Ah[r][cc+0] = hx; Ah[r][cc+1] = hy; Ah[r][cc+2] = hz; Ah[r][cc+3] = hw;
            Al[r][cc+0] = to_tf32(v.x - hx); Al[r][cc+1] = to_tf32(v.y - hy);
            Al[r][cc+2] = to_tf32(v.z - hz); Al[r][cc+3] = to_tf32(v.w - hw);
        }
        #pragma unroll
        for (int i = 0; i < 4; i++) {
            int f = tid + i*256;
            int r = f >> 3, cc = (f & 7) * 4;
            float4 v = *(const float4*)&Bz[(size_t)(col0 + r)*128 + k0 + cc];
            float hx = to_tf32(v.x), hy = to_tf32(v.y), hz = to_tf32(v.z), hw = to_tf32(v.w);
            Bh[r][cc+0] = hx; Bh[r][cc+1] = hy; Bh[r][cc+2] = hz; Bh[r][cc+3] = hw;
            Bl[r][cc+0] = to_tf32(v.x - hx); Bl[r][cc+1] = to_tf32(v.y - hy);
            Bl[r][cc+2] = to_tf32(v.z - hz); Bl[r][cc+3] = to_tf32(v.w - hw);
        }
        __syncthreads();
        #pragma unroll
        for (int ks = 0; ks < 4; ks++) {
            int kk = ks * 8;
            uint32_t ah[2][4], al[2][4];
            #pragma unroll
            for (int mt = 0; mt < 2; mt++) {
                int m0 = wm + mt*16;
                ah[mt][0] = __float_as_uint(Ah[m0 + g    ][kk + tg    ]);
                ah[mt][1] = __float_as_uint(Ah[m0 + g + 8][kk + tg    ]);
                ah[mt][2] = __float_as_uint(Ah[m0 + g    ][kk + tg + 4]);
                ah[mt][3] = __float_as_uint(Ah[m0 + g + 8][kk + tg + 4]);
                al[mt][0] = __float_as_uint(Al[m0 + g    ][kk + tg    ]);
                al[mt][1] = __float_as_uint(Al[m0 + g + 8][kk + tg    ]);
                al[mt][2] = __float_as_uint(Al[m0 + g    ][kk + tg + 4]);
                al[mt][3] = __float_as_uint(Al[m0 + g + 8][kk + tg + 4]);
            }
            #pragma unroll
            for (int nt = 0; nt < 8; nt++) {
                int n0 = wn + nt*8 + g;
                uint32_t bh[2], bl[2];
                bh[0] = __float_as_uint(Bh[n0][kk + tg    ]);
                bh[1] = __float_as_uint(Bh[n0][kk + tg + 4]);
                bl[0] = __float_as_uint(Bl[n0][kk + tg    ]);
                bl[1] = __float_as_uint(Bl[n0][kk + tg + 4]);
                #pragma unroll
                for (int mt = 0; mt < 2; mt++) {
                    mma_tf32(c[mt][nt], ah[mt], bh);
                    mma_tf32(c[mt][nt], ah[mt], bl);
                    mma_tf32(c[mt][nt], al[mt], bh);
                }
            }
        }
        __syncthreads();
    }

    #pragma unroll
    for (int mt = 0; mt < 2; mt++) {
        int row = row0 + wm + mt*16 + g;
        #pragma unroll
        for (int nt = 0; nt < 8; nt++) {
            int col = col0 + wn + nt*8 + tg*2;
            *(float2*)&Cz[(size_t)row*N + col]     = make_float2(c[mt][nt][0], c[mt][nt][1]);
            *(float2*)&Cz[(size_t)(row+8)*N + col] = make_float2(c[mt][nt][2], c[mt][nt][3]);
        }
    }
}

// ---------------- 2d) batched NN 3xTF32 value GEMM with gated epilogue -------
// C[z][512][128] = P[z][512][1536] @ V[z][1536][128]; out *= g, scattered to wvg.
__global__ void __launch_bounds__(256, 2)
gemm_val3x_kernel() {
    extern __shared__ float sm[];
    float (*Ah)[36]  = (float(*)[36])sm;
    float (*Al)[36]  = (float(*)[36])(sm + 128*36);
    float (*Bh)[132] = (float(*)[132])(sm + 2*128*36);
    float (*Bl)[132] = (float(*)[132])(sm + 2*128*36 + 32*132);

    int z = blockIdx.z;
    int b = z >> 3, h = z & 7;
    const float* Az = g_S1 + (size_t)z * Ll * WTOT;
    const float* Bz = g_vals + (size_t)z * WTOT * DVv;

    int tid  = threadIdx.x;
    int warp = tid >> 5, lane = tid & 31;
    int g  = lane >> 2, tg = lane & 3;
    int wm = (warp >> 1) * 32;
    int wn = (warp & 1) * 64;
    int row0 = blockIdx.y * 128;

    float c[2][8][4];
    #pragma unroll
    for (int mt = 0; mt < 2; mt++)
        #pragma unroll
        for (int nt = 0; nt < 8; nt++)
            #pragma unroll
            for (int j = 0; j < 4; j++) c[mt][nt][j] = 0.f;

    for (int k0 = 0; k0 < WTOT; k0 += 32) {
        #pragma unroll
        for (int i = 0; i < 4; i++) {
            int f = tid + i*256;
            int r = f >> 3, cc = (f & 7) * 4;
            float4 v = *(const float4*)&Az[(size_t)(row0 + r)*WTOT + k0 + cc];
            float hx = to_tf32(v.x), hy = to_tf32(v.y), hz = to_tf32(v.z), hw = to_tf32(v.w);
            Ah[r][cc+0] = hx; Ah[r][cc+1] = hy; Ah[r][cc+2] = hz; Ah[r][cc+3] = hw;
            Al[r][cc+0] = to_tf32(v.x - hx); Al[r][cc+1] = to_tf32(v.y - hy);
            Al[r][cc+2] = to_tf32(v.z - hz); Al[r][cc+3] = to_tf32(v.w - hw);
        }
        #pragma unroll
        for (int i = 0; i < 4; i++) {
            int f = tid + i*256;
            int r = f >> 5, cc = (f & 31) * 4;
            float4 v = *(const float4*)&Bz[(size_t)(k0 + r)*128 + cc];
            float hx = to_tf32(v.x), hy = to_tf32(v.y), hz = to_tf32(v.z), hw = to_tf32(v.w);
            Bh[r][cc+0] = hx; Bh[r][cc+1] = hy; Bh[r][cc+2] = hz; Bh[r][cc+3] = hw;
            Bl[r][cc+0] = to_tf32(v.x - hx); Bl[r][cc+1] = to_tf32(v.y - hy);
            Bl[r][cc+2] = to_tf32(v.z - hz); Bl[r][cc+3] = to_tf32(v.w - hw);
        }
        __syncthreads();
        #pragma unroll
        for (int ks = 0; ks < 4; ks++) {
            int kk = ks * 8;
            uint32_t ah[2][4], al[2][4];
            #pragma unroll
            for (int mt = 0; mt < 2; mt++) {
                int m0 = wm + mt*16;
                ah[mt][0] = __float_as_uint(Ah[m0 + g    ][kk + tg    ]);
                ah[mt][1] = __float_as_uint(Ah[m0 + g + 8][kk + tg    ]);
                ah[mt][2] = __float_as_uint(Ah[m0 + g    ][kk + tg + 4]);
                ah[mt][3] = __float_as_uint(Ah[m0 + g + 8][kk + tg + 4]);
                al[mt][0] = __float_as_uint(Al[m0 + g    ][kk + tg    ]);
                al[mt][1] = __float_as_uint(Al[m0 + g + 8][kk + tg    ]);
                al[mt][2] = __float_as_uint(Al[m0 + g    ][kk + tg + 4]);
                al[mt][3] = __float_as_uint(Al[m0 + g + 8][kk + tg + 4]);
            }
            #pragma unroll
            for (int nt = 0; nt < 8; nt++) {
                int n0 = wn + nt*8 + g;
                uint32_t bh[2], bl[2];
                bh[0] = __float_as_uint(Bh[kk + tg    ][n0]);
                bh[1] = __float_as_uint(Bh[kk + tg + 4][n0]);
                bl[0] = __float_as_uint(Bl[kk + tg    ][n0]);
                bl[1] = __float_as_uint(Bl[kk + tg + 4][n0]);
                #pragma unroll
                for (int mt = 0; mt < 2; mt++) {
                    mma_tf32(c[mt][nt], ah[mt], bh);
                    mma_tf32(c[mt][nt], ah[mt], bl);
                    mma_tf32(c[mt][nt], al[mt], bh);
                }
            }
        }
        __syncthreads();
    }

    // epilogue: wv * gate -> g_wvg[(b*512+l)*1024 + h*128 + dv]
    #pragma unroll
    for (int mt = 0; mt < 2; mt++) {
        int row = row0 + wm + mt*16 + g;
        #pragma unroll
        for (int nt = 0; nt < 8; nt++) {
            int col = wn + nt*8 + tg*2;
            size_t o0 = ((size_t)(b*Ll + row))*1024 + h*128 + col;
            size_t o1 = ((size_t)(b*Ll + row + 8))*1024 + h*128 + col;
            float2 g0 = *(const float2*)&g_g[o0];
            float2 g1 = *(const float2*)&g_g[o1];
            *(float2*)&g_wvg[o0] = make_float2(c[mt][nt][0]*g0.x, c[mt][nt][1]*g0.y);
            *(float2*)&g_wvg[o1] = make_float2(c[mt][nt][2]*g1.x, c[mt][nt][3]*g1.y);
        }
    }
}

// ---------------- 3) per-head LN of q and k, qu/qv, v copy, gate -------------
__global__ void qkln_kernel(const float* __restrict__ xu, const float* __restrict__ xv) {
    __shared__ float sh[4];
    int bl = blockIdx.x, h = blockIdx.y, t = threadIdx.x;
    int b = bl >> 9, l = bl & 511;
    size_t bh = (size_t)(b*Hh + h);

    float x  = g_qraw[(size_t)bl*1024 + h*128 + t];
    float mu = blockReduceSum128(x, sh) * (1.f/128.f);
    float d  = x - mu;
    float var = blockReduceSum128(d*d, sh) * (1.f/128.f);
    float qn = d * rsqrtf(var + 1e-6f);
    g_qu[(bh*Ll + l)*128 + t] = qn + xu[h*128 + t];
    g_qv[(bh*Ll + l)*128 + t] = qn + xv[h*128 + t];

    x  = g_kvg[(size_t)bl*3072 + h*128 + t];
    mu = blockReduceSum128(x, sh) * (1.f/128.f);
    d  = x - mu;
    var = blockReduceSum128(d*d, sh) * (1.f/128.f);
    g_kn[(bh*Ll + l)*128 + t] = d * rsqrtf(var + 1e-6f);

    g_vals[(bh*WTOT + Mm + l)*128 + t] = g_kvg[(size_t)bl*3072 + 1024 + h*128 + t];

    float gx = g_kvg[(size_t)bl*3072 + 2048 + h*128 + t];
    g_g[(size_t)bl*1024 + h*128 + t] = gx / (1.f + __expf(-gx));
}

// ---------------- 4) VQ argmin over 512 codes --------------------------------
__global__ void vq_kernel(const float* __restrict__ codebook) {
    __shared__ float ks[16][128];
    __shared__ float redv[16][256];
    __shared__ int   redi[16][256];
    int bh = blockIdx.x, lt = blockIdx.y;
    int h  = bh & 7;
    int tid = threadIdx.x;
    #pragma unroll
    for (int j = 0; j < 2; j++) {
        int f = tid + j*256;
        int r = f >> 5, c4 = f & 31;
        *(float4*)&ks[r][c4*4] =
            *(const float4*)&g_kn[((size_t)bh*Ll + lt*16 + r)*128 + c4*4];
    }
    __syncthreads();

    float best[16]; int bidx[16];
    #pragma unroll
    for (int r = 0; r < 16; r++) { best[r] = 3.4e38f; bidx[r] = 0; }

    for (int s = tid; s < Ss; s += 256) {
        const float4* c = (const float4*)(codebook + ((size_t)h*Ss + s)*128);
        float cc = 0.f; float acc[16];
        #pragma unroll
        for (int r = 0; r < 16; r++) acc[r] = 0.f;
        #pragma unroll 4
        for (int d4 = 0; d4 < 32; d4++) {
            float4 cv = c[d4];
            cc += cv.x*cv.x + cv.y*cv.y + cv.z*cv.z + cv.w*cv.w;
            #pragma unroll
            for (int r = 0; r < 16; r++) {
                float4 kv = *(float4*)&ks[r][d4*4];
                acc[r] += cv.x*kv.x + cv.y*kv.y + cv.z*kv.z + cv.w*kv.w;
            }
        }
        #pragma unroll
        for (int r = 0; r < 16; r++) {
            float d2 = cc - 2.f*acc[r];
            if (d2 < best[r]) { best[r] = d2; bidx[r] = s; }
        }
    }
    #pragma unroll
    for (int r = 0; r < 16; r++) { redv[r][tid] = best[r]; redi[r][tid] = bidx[r]; }
    __syncthreads();

    int warp = tid >> 5, lane = tid & 31;
    for (int r = warp*2; r < warp*2 + 2; r++) {
        float bv = 3.4e38f; int bi = 0x7fffffff;
        for (int t = lane; t < 256; t += 32) {
            float v = redv[r][t]; int i = redi[r][t];
            if (v < bv || (v == bv && i < bi)) { bv = v; bi = i; }
        }
        #pragma unroll
        for (int o = 16; o > 0; o >>= 1) {
            float ov = __shfl_xor_sync(0xffffffffu, bv, o);
            int   oi = __shfl_xor_sync(0xffffffffu, bi, o);
            if (ov < bv || (ov == bv && oi < bi)) { bv = ov; bi = oi; }
        }
        if (lane == 0) g_z[(size_t)bh*Ll + lt*16 + r] = bi;
    }
}

// ---------------- 5) assemble keys / vals ------------------------------------
__global__ void assemble_kernel(const float* __restrict__ xlk, const float* __restrict__ xlv,
                                const float* __restrict__ codebook,
                                const float* __restrict__ aggU) {
    for (int e = blockIdx.x*blockDim.x + threadIdx.x; e < Bb*Hh*Mm*DKk;
         e += gridDim.x*blockDim.x) {
        int bh  = e >> 16;
        int rem = e & 65535;
        int m = rem >> 7, d = rem & 127;
        g_keys[((size_t)bh*WTOT + m)*128 + d] = xlk[e];
        g_vals[((size_t)bh*WTOT + m)*128 + d] = xlv[e];
        int s = g_z[(size_t)bh*Ll + m];
        int h = bh & 7;
        g_keys[((size_t)bh*WTOT + Mm + m)*128 + d] = codebook[((size_t)h*Ss + s)*128 + d];
        // cache block: codebook rows + agg_upper values
        g_keys[((size_t)bh*WTOT + WREC + m)*128 + d] = codebook[((size_t)h*Ss + m)*128 + d];
        g_vals[((size_t)bh*WTOT + WREC + m)*128 + d] = aggU[e];
    }
}

// ---------------- 6) softmax: combine AC + shifted BD + cache bias -----------
// grid (L, 64), 128 threads. Probs (pre-scaled by inv_d) overwrite g_S1.
__global__ void softmax_kernel(const float* __restrict__ aggL) {
    __shared__ float red[4];
    int l = blockIdx.x, z = blockIdx.y, tid = threadIdx.x;
    float* S1row = g_S1 + ((size_t)z*Ll + l)*WTOT;
    const float* S2row = g_S2 + ((size_t)z*Ll + l)*WREC;
    int limit = l + Mm;

    float sv[12];
    float m = -3.4e38f;
    #pragma unroll
    for (int i = 0; i < 12; i++) {
        int w = tid + i*128;
        float s;
        if (w < WREC) {
            s = (w <= limit) ? (S1row[w] + S2row[w + 511 - l]) * INVTAU : -3.4e38f;
        } else {
            float al = aggL[(size_t)z*Ss + (w - WREC)];
            float bias = (al > 0.f) ? logf(fmaxf(al, 1e-30f)) : -1e30f;
            s = S1row[w] * INVTAU + bias;
        }
        sv[i] = s;
        m = fmaxf(m, s);
    }
    #pragma unroll
    for (int o = 16; o > 0; o >>= 1) m = fmaxf(m, __shfl_xor_sync(0xffffffffu, m, o));
    if ((tid & 31) == 0) red[tid >> 5] = m;
    __syncthreads();
    m = fmaxf(fmaxf(red[0], red[1]), fmaxf(red[2], red[3]));
    __syncthreads();

    float ssum = 0.f;
    #pragma unroll
    for (int i = 0; i < 12; i++) {
        float p = (sv[i] > -1e37f) ? __expf(sv[i] - m) : 0.f;
        sv[i] = p;
        ssum += p;
    }
    #pragma unroll
    for (int o = 16; o > 0; o >>= 1) ssum += __shfl_xor_sync(0xffffffffu, ssum, o);
    if ((tid & 31) == 0) red[tid >> 5] = ssum;
    __syncthreads();
    float invd = 1.f / (red[0] + red[1] + red[2] + red[3]);

    #pragma unroll
    for (int i = 0; i < 12; i++) S1row[tid + i*128] = sv[i] * invd;
}

// ---------------- launch ------------------------------------------------------
extern "C" void kernel_launch(void* const* d_in, const int* in_sizes, int n_in,
                              void* d_out, int out_size) {
    const float* input = (const float*)d_in[0];
    const float* xlk   = (const float*)d_in[2];
    const float* xlv   = (const float*)d_in[3];
    const float* aggU  = (const float*)d_in[4];
    const float* aggL  = (const float*)d_in[5];
    const float* Wq    = (const float*)d_in[6];
    const float* Wkvg  = (const float*)d_in[7];
    const float* Wres  = (const float*)d_in[8];
    const float* xu    = (const float*)d_in[9];
    const float* xv    = (const float*)d_in[10];
    const float* xlr   = (const float*)d_in[11];
    const float* cb    = (const float*)d_in[12];
    float* out = (float*)d_out;

    float *xt, *qraw, *kvg, *wvg, *qu, *qv, *keys, *S1, *S2;
    cudaGetSymbolAddress((void**)&xt,   g_xt);
    cudaGetSymbolAddress((void**)&qraw, g_qraw);
    cudaGetSymbolAddress((void**)&kvg,  g_kvg);
    cudaGetSymbolAddress((void**)&wvg,  g_wvg);
    cudaGetSymbolAddress((void**)&qu,   g_qu);
    cudaGetSymbolAddress((void**)&qv,   g_qv);
    cudaGetSymbolAddress((void**)&keys, g_keys);
    cudaGetSymbolAddress((void**)&S1,   g_S1);
    cudaGetSymbolAddress((void**)&S2,   g_S2);

    const int nt3x_smem = 4*128*36*4;                     // 73728
    const int val3x_smem = (2*128*36 + 2*32*132)*4;       // 70656
    cudaFuncSetAttribute(gemm_nt3x_kernel,  cudaFuncAttributeMaxDynamicSharedMemorySize, nt3x_smem);
    cudaFuncSetAttribute(gemm_val3x_kernel, cudaFuncAttributeMaxDynamicSharedMemorySize, val3x_smem);

    ln_input_kernel<<<Bb*Ll, 256>>>(input);
    // q projection: tf32 (continuous consumer)
    gemm_tf32_kernel<<<dim3(1024/128, 4096/128), 256>>>(xt, Wq, qraw, 4096, 1024, 1024);
    // kvg: k columns fp32 (feeds discrete VQ argmin); v,g columns tf32
    gemm_ffma_kernel<<<dim3(1024/128, 4096/128), 256>>>(xt, Wkvg, kvg, 4096, 3072, 1024);
    gemm_tf32_kernel<<<dim3(2048/128, 4096/128), 256>>>(xt, Wkvg + 1024, kvg + 1024,
                                                        4096, 3072, 1024);
    qkln_kernel<<<dim3(Bb*Ll, Hh), 128>>>(xu, xv);
    vq_kernel<<<dim3(Bb*Hh, Ll/16), 256>>>(cb);
    assemble_kernel<<<4096, 256>>>(xlk, xlv, cb, aggU);

    // S1 = qu @ keys^T  (per bh)
    gemm_nt3x_kernel<<<dim3(WTOT/128, Ll/128, 64), 256, nt3x_smem>>>(
        qu, keys, S1, WTOT,
        (size_t)Ll*128, (size_t)WTOT*128, (size_t)Ll*WTOT, 0);
    // S2 = qv @ xlr^T  (B per head)
    gemm_nt3x_kernel<<<dim3(WREC/128, Ll/128, 64), 256, nt3x_smem>>>(
        qv, xlr, S2, WREC,
        (size_t)Ll*128, (size_t)WREC*128, (size_t)Ll*WREC, 1);

    softmax_kernel<<<dim3(Ll, 64), 128>>>(aggL);

    // wv = P @ vals, gated epilogue
    gemm_val3x_kernel<<<dim3(1, Ll/128, 64), 256, val3x_smem>>>();

    gemm_tf32_kernel<<<dim3(1024/128, 4096/128), 256>>>(wvg, Wres, out, 4096, 1024, 1024);
}

// round 6
// speedup vs baseline: 5.7216x; 1.1191x over previous
#include <cuda_runtime.h>
#include <cuda_bf16.h>
#include <math.h>
#include <stdint.h>

// Shapes (fixed for this problem)
#define Bb   8
#define Ll   512
#define Mm   512
#define Hh   8
#define DKk  128
#define DVv  128
#define Ss   512
#define DMm  1024
#define WREC 1024
#define WTOT 1536    // recent 1024 + cache 512

#define INVTAU 0.08838834764831845f   // 1/sqrt(128)

// ---------------- scratch (device globals; no allocation allowed) ------------
__device__ float g_xt  [Bb*Ll*DMm];
__device__ float g_qraw[Bb*Ll*Hh*DKk];
__device__ float g_kvg [Bb*Ll*3072];
__device__ float g_kn  [Bb*Hh*Ll*DKk];
__device__ float g_g   [Bb*Ll*Hh*DVv];
__device__ float g_qu  [64*Ll*DKk];          // q + x_u  (b,h,l,d)
__device__ float g_qv  [64*Ll*DKk];          // q + x_v
__device__ float g_keys[64*WTOT*DKk];        // [xl_k_hat; c_z gather; codebook]
__device__ float g_vals[64*WTOT*DVv];        // [xl_v; v; agg_upper]
__device__ float g_S1  [(size_t)64*Ll*WTOT]; // scores -> probs
__device__ float g_S2  [(size_t)64*Ll*WREC]; // BD term
__device__ float g_wvg [Bb*Ll*Hh*DVv];
__device__ int   g_z   [Bb*Hh*Ll];

// ---------------- helpers ----------------------------------------------------
__device__ __forceinline__ float to_tf32(float x) {
    uint32_t u;
    asm("cvt.rna.tf32.f32 %0, %1;" : "=r"(u) : "f"(x));
    return __uint_as_float(u);
}

__device__ __forceinline__ void mma_tf32(float* c, const uint32_t* a, const uint32_t* b) {
    asm volatile(
        "mma.sync.aligned.m16n8k8.row.col.f32.tf32.tf32.f32 "
        "{%0,%1,%2,%3}, {%4,%5,%6,%7}, {%8,%9}, {%0,%1,%2,%3};"
        : "+f"(c[0]), "+f"(c[1]), "+f"(c[2]), "+f"(c[3])
        : "r"(a[0]), "r"(a[1]), "r"(a[2]), "r"(a[3]), "r"(b[0]), "r"(b[1]));
}

__device__ __forceinline__ void mma_bf16(float* c, const uint32_t* a, const uint32_t* b) {
    asm volatile(
        "mma.sync.aligned.m16n8k16.row.col.f32.bf16.bf16.f32 "
        "{%0,%1,%2,%3}, {%4,%5,%6,%7}, {%8,%9}, {%0,%1,%2,%3};"
        : "+f"(c[0]), "+f"(c[1]), "+f"(c[2]), "+f"(c[3])
        : "r"(a[0]), "r"(a[1]), "r"(a[2]), "r"(a[3]), "r"(b[0]), "r"(b[1]));
}

// split two floats into packed bf16x2 hi and lo words (k-pair: x->low, y->high)
__device__ __forceinline__ void split2(float x, float y, uint32_t& hi, uint32_t& lo) {
    __nv_bfloat162 h = __floats2bfloat162_rn(x, y);
    float hx = __bfloat162float(h.x), hy = __bfloat162float(h.y);
    __nv_bfloat162 l = __floats2bfloat162_rn(x - hx, y - hy);
    hi = *(uint32_t*)&h;
    lo = *(uint32_t*)&l;
}

__device__ __forceinline__ float blockReduceSum256(float v, float* sh) {
    #pragma unroll
    for (int o = 16; o > 0; o >>= 1) v += __shfl_xor_sync(0xffffffffu, v, o);
    __syncthreads();
    if ((threadIdx.x & 31) == 0) sh[threadIdx.x >> 5] = v;
    __syncthreads();
    float r = 0.f;
    #pragma unroll
    for (int i = 0; i < 8; i++) r += sh[i];
    return r;
}

__device__ __forceinline__ float blockReduceSum128(float v, float* sh) {
    #pragma unroll
    for (int o = 16; o > 0; o >>= 1) v += __shfl_xor_sync(0xffffffffu, v, o);
    __syncthreads();
    if ((threadIdx.x & 31) == 0) sh[threadIdx.x >> 5] = v;
    __syncthreads();
    return sh[0] + sh[1] + sh[2] + sh[3];
}

// ---------------- 1) LayerNorm of input (rows of 1024) -----------------------
__global__ void ln_input_kernel(const float* __restrict__ x) {
    __shared__ float sh[8];
    size_t base = (size_t)blockIdx.x * DMm;
    float lv[4]; float s = 0.f;
    #pragma unroll
    for (int j = 0; j < 4; j++) { lv[j] = x[base + threadIdx.x + j*256]; s += lv[j]; }
    float mu = blockReduceSum256(s, sh) * (1.f/1024.f);
    float s2 = 0.f;
    #pragma unroll
    for (int j = 0; j < 4; j++) { float d = lv[j] - mu; s2 += d*d; }
    float var = blockReduceSum256(s2, sh) * (1.f/1024.f);
    float rstd = rsqrtf(var + 1e-6f);
    #pragma unroll
    for (int j = 0; j < 4; j++) g_xt[base + threadIdx.x + j*256] = (lv[j]-mu)*rstd;
}

// ---------------- 2a) fp32 FFMA GEMM (full precision, k-columns) -------------
__global__ void __launch_bounds__(256, 2)
gemm_ffma_kernel(const float* __restrict__ A, const float* __restrict__ B,
                 float* __restrict__ C, int M, int N, int K) {
    __shared__ float As[16][132];
    __shared__ float Bs[16][132];
    int tid  = threadIdx.x;
    int row0 = blockIdx.y * 128;
    int col0 = blockIdx.x * 128;
    int tx = tid & 15, ty = tid >> 4;

    float acc[8][8];
    #pragma unroll
    for (int i = 0; i < 8; i++)
        #pragma unroll
        for (int j = 0; j < 8; j++) acc[i][j] = 0.f;

    for (int k0 = 0; k0 < K; k0 += 16) {
        #pragma unroll
        for (int i = 0; i < 2; i++) {
            int f = tid + i*256;
            int r = f >> 2, c4 = f & 3;
            float4 v = *(const float4*)&A[(size_t)(row0 + r)*K + k0 + c4*4];
            As[c4*4+0][r] = v.x; As[c4*4+1][r] = v.y;
            As[c4*4+2][r] = v.z; As[c4*4+3][r] = v.w;
        }
        #pragma unroll
        for (int i = 0; i < 2; i++) {
            int f = tid + i*256;
            int r = f >> 5, c4 = f & 31;
            *(float4*)&Bs[r][c4*4] = *(const float4*)&B[(size_t)(k0 + r)*N + col0 + c4*4];
        }
        __syncthreads();
        #pragma unroll
        for (int kk = 0; kk < 16; kk++) {
            float a[8], bb[8];
            *(float4*)&a[0]  = *(float4*)&As[kk][ty*8];
            *(float4*)&a[4]  = *(float4*)&As[kk][ty*8 + 4];
            *(float4*)&bb[0] = *(float4*)&Bs[kk][tx*4];
            *(float4*)&bb[4] = *(float4*)&Bs[kk][64 + tx*4];
            #pragma unroll
            for (int i = 0; i < 8; i++)
                #pragma unroll
                for (int j = 0; j < 8; j++) acc[i][j] += a[i]*bb[j];
        }
        __syncthreads();
    }
    #pragma unroll
    for (int i = 0; i < 8; i++) {
        size_t crow = (size_t)(row0 + ty*8 + i)*N;
        *(float4*)&C[crow + col0 + tx*4]      = make_float4(acc[i][0], acc[i][1], acc[i][2], acc[i][3]);
        *(float4*)&C[crow + col0 + 64 + tx*4] = make_float4(acc[i][4], acc[i][5], acc[i][6], acc[i][7]);
    }
}

// ---------------- 2b) tf32 tensor-core GEMM (continuous projections) ---------
__global__ void __launch_bounds__(256, 2)
gemm_tf32_kernel(const float* __restrict__ A, const float* __restrict__ B,
                 float* __restrict__ C, int M, int N, int K) {
    __shared__ float As[128][36];
    __shared__ float Bs[32][132];
    int tid  = threadIdx.x;
    int warp = tid >> 5, lane = tid & 31;
    int g  = lane >> 2, tg = lane & 3;
    int wm = (warp >> 1) * 32;
    int wn = (warp & 1) * 64;
    int row0 = blockIdx.y * 128;
    int col0 = blockIdx.x * 128;

    float c[2][8][4];
    #pragma unroll
    for (int mt = 0; mt < 2; mt++)
        #pragma unroll
        for (int nt = 0; nt < 8; nt++)
            #pragma unroll
            for (int j = 0; j < 4; j++) c[mt][nt][j] = 0.f;

    for (int k0 = 0; k0 < K; k0 += 32) {
        #pragma unroll
        for (int i = 0; i < 4; i++) {
            int f = tid + i*256;
            int r = f >> 3, cc = (f & 7) * 4;
            float4 v = *(const float4*)&A[(size_t)(row0 + r)*K + k0 + cc];
            As[r][cc+0] = to_tf32(v.x); As[r][cc+1] = to_tf32(v.y);
            As[r][cc+2] = to_tf32(v.z); As[r][cc+3] = to_tf32(v.w);
        }
        #pragma unroll
        for (int i = 0; i < 4; i++) {
            int f = tid + i*256;
            int r = f >> 5, cc = (f & 31) * 4;
            float4 v = *(const float4*)&B[(size_t)(k0 + r)*N + col0 + cc];
            Bs[r][cc+0] = to_tf32(v.x); Bs[r][cc+1] = to_tf32(v.y);
            Bs[r][cc+2] = to_tf32(v.z); Bs[r][cc+3] = to_tf32(v.w);
        }
        __syncthreads();
        #pragma unroll
        for (int ks = 0; ks < 4; ks++) {
            int kk = ks * 8;
            uint32_t a[2][4], b[8][2];
            #pragma unroll
            for (int mt = 0; mt < 2; mt++) {
                int m0 = wm + mt*16;
                a[mt][0] = __float_as_uint(As[m0 + g    ][kk + tg    ]);
                a[mt][1] = __float_as_uint(As[m0 + g + 8][kk + tg    ]);
                a[mt][2] = __float_as_uint(As[m0 + g    ][kk + tg + 4]);
                a[mt][3] = __float_as_uint(As[m0 + g + 8][kk + tg + 4]);
            }
            #pragma unroll
            for (int nt = 0; nt < 8; nt++) {
                int n0 = wn + nt*8 + g;
                b[nt][0] = __float_as_uint(Bs[kk + tg    ][n0]);
                b[nt][1] = __float_as_uint(Bs[kk + tg + 4][n0]);
            }
            #pragma unroll
            for (int mt = 0; mt < 2; mt++)
                #pragma unroll
                for (int nt = 0; nt < 8; nt++)
                    mma_tf32(c[mt][nt], a[mt], b[nt]);
        }
        __syncthreads();
    }

    #pragma unroll
    for (int mt = 0; mt < 2; mt++) {
        int row = row0 + wm + mt*16 + g;
        #pragma unroll
        for (int nt = 0; nt < 8; nt++) {
            int col = col0 + wn + nt*8 + tg*2;
            *(float2*)&C[(size_t)row*N + col]     = make_float2(c[mt][nt][0], c[mt][nt][1]);
            *(float2*)&C[(size_t)(row+8)*N + col] = make_float2(c[mt][nt][2], c[mt][nt][3]);
        }
    }
}

// ---------------- 2c) batched NT bf16 3-term GEMM: C[z] = A[z] @ B[z]^T ------
// A: [M][128] row-major, B: [N][128] row-major. hi/lo bf16 split, 3 products.
__global__ void __launch_bounds__(256, 2)
gemm_ntbf_kernel(const float* __restrict__ A, const float* __restrict__ B,
                 float* __restrict__ C, int N,
                 size_t strideA, size_t strideB, size_t strideC, int bPerHead) {
    __shared__ uint32_t Ah[128][20], Al[128][20], Bh[128][20], Bl[128][20];

    int z = blockIdx.z;
    const float* Az = A + (size_t)z * strideA;
    const float* Bz = B + (size_t)(bPerHead ? (z & 7) : z) * strideB;
    float* Cz = C + (size_t)z * strideC;

    int tid  = threadIdx.x;
    int warp = tid >> 5, lane = tid & 31;
    int g  = lane >> 2, tg = lane & 3;
    int wm = (warp >> 1) * 32;
    int wn = (warp & 1) * 64;
    int row0 = blockIdx.y * 128;
    int col0 = blockIdx.x * 128;

    float c[2][8][4];
    #pragma unroll
    for (int mt = 0; mt < 2; mt++)
        #pragma unroll
        for (int nt = 0; nt < 8; nt++)
            #pragma unroll
            for (int j = 0; j < 4; j++) c[mt][nt][j] = 0.f;

    for (int k0 = 0; k0 < 128; k0 += 32) {
        #pragma unroll
        for (int i = 0; i < 4; i++) {
            int f = tid + i*256;
            int r = f >> 3, q4 = f & 7;
            float4 v = *(const float4*)&Az[(size_t)(row0 + r)*128 + k0 + q4*4];
            split2(v.x, v.y, Ah[r][2*q4],   Al[r][2*q4]);
            split2(v.z, v.w, Ah[r][2*q4+1], Al[r][2*q4+1]);
        }
        #pragma unroll
        for (int i = 0; i < 4; i++) {
            int f = tid + i*256;
            int r = f >> 3, q4 = f & 7;
            float4 v = *(const float4*)&Bz[(size_t)(col0 + r)*128 + k0 + q4*4];
            split2(v.x, v.y, Bh[r][2*q4],   Bl[r][2*q4]);
            split2(v.z, v.w, Bh[r][2*q4+1], Bl[r][2*q4+1]);
        }
        __syncthreads();
        #pragma unroll
        for (int c16 = 0; c16 < 2; c16++) {
            int coff = c16 * 8;
            uint32_t ah[2][4], al[2][4];
            #pragma unroll
            for (int mt = 0; mt < 2; mt++) {
                int m0 = wm + mt*16;
                ah[mt][0] = Ah[m0 + g    ][coff + tg    ];
                ah[mt][1] = Ah[m0 + g + 8][coff + tg    ];
                ah[mt][2] = Ah[m0 + g    ][coff + tg + 4];
                ah[mt][3] = Ah[m0 + g + 8][coff + tg + 4];
                al[mt][0] = Al[m0 + g    ][coff + tg    ];
                al[mt][1] = Al[m0 + g + 8][coff + tg    ];
                al[mt][2] = Al[m0 + g    ][coff + tg + 4];
                al[mt][3] = Al[m0 + g + 8][coff + tg + 4];
            }
            #pragma unroll
            for (int nt = 0; nt < 8; nt++) {
                int n0 = wn + nt*8 + g;
                uint32_t bh[2], bl[2];
                bh[0] = Bh[n0][coff + tg    ];
                bh[1] = Bh[n0][coff + tg + 4];
                bl[0] = Bl[n0][coff + tg    ];
                bl[1] = Bl[n0][coff + tg + 4];
                #pragma unroll
                for (int mt = 0; mt < 2; mt++) {
                    mma_bf16(c[mt][nt], ah[mt], bh);
                    mma_bf16(c[mt][nt], ah[mt], bl);
                    mma_bf16(c[mt][nt], al[mt], bh);
                }
            }
        }
        __syncthreads();
    }

    #pragma unroll
    for (int mt = 0; mt < 2; mt++) {
        int row = row0 + wm + mt*16 + g;
        #pragma unroll
        for (int nt = 0; nt < 8; nt++) {
            int col = col0 + wn + nt*8 + tg*2;
            *(float2*)&Cz[(size_t)row*N + col]     = make_float2(c[mt][nt][0], c[mt][nt][1]);
            *(float2*)&Cz[(size_t)(row+8)*N + col] = make_float2(c[mt][nt][2], c[mt][nt][3]);
        }
    }
}

// ---------------- 2d) batched NN bf16 3-term value GEMM, gated epilogue ------
// C[z][512][128] = P[z][512][1536] @ V[z][1536][128]; out *= g, scatter to wvg.
__global__ void __launch_bounds__(256, 2)
gemm_valbf_kernel() {
    __shared__ uint32_t Ah[128][20], Al[128][20];
    __shared__ uint32_t BhT[16][136], BlT[16][136];   // [k-pair][n], pad 136 (mod32==8)

    int z = blockIdx.z;
    int b = z >> 3, h = z & 7;
    const float* Az = g_S1 + (size_t)z * Ll * WTOT;
    const float* Bz = g_vals + (size_t)z * WTOT * DVv;

    int tid  = threadIdx.x;
    int warp = tid >> 5, lane = tid & 31;
    int g  = lane >> 2, tg = lane & 3;
    int wm = (warp >> 1) * 32;
    int wn = (warp & 1) * 64;
    int row0 = blockIdx.y * 128;

    float c[2][8][4];
    #pragma unroll
    for (int mt = 0; mt < 2; mt++)
        #pragma unroll
        for (int nt = 0; nt < 8; nt++)
            #pragma unroll
            for (int j = 0; j < 4; j++) c[mt][nt][j] = 0.f;

    for (int k0 = 0; k0 < WTOT; k0 += 32) {
        #pragma unroll
        for (int i = 0; i < 4; i++) {
            int f = tid + i*256;
            int r = f >> 3, q4 = f & 7;
            float4 v = *(const float4*)&Az[(size_t)(row0 + r)*WTOT + k0 + q4*4];
            split2(v.x, v.y, Ah[r][2*q4],   Al[r][2*q4]);
            split2(v.z, v.w, Ah[r][2*q4+1], Al[r][2*q4+1]);
        }
        // B: pack k-pairs along rows of V ([k][n] row-major)
        #pragma unroll
        for (int i = 0; i < 2; i++) {
            int f = tid + i*256;
            int kp = f >> 5, n4 = f & 31;
            float4 v0 = *(const float4*)&Bz[(size_t)(k0 + 2*kp    )*128 + n4*4];
            float4 v1 = *(const float4*)&Bz[(size_t)(k0 + 2*kp + 1)*128 + n4*4];
            split2(v0.x, v1.x, BhT[kp][4*n4+0], BlT[kp][4*n4+0]);
            split2(v0.y, v1.y, BhT[kp][4*n4+1], BlT[kp][4*n4+1]);
            split2(v0.z, v1.z, BhT[kp][4*n4+2], BlT[kp][4*n4+2]);
            split2(v0.w, v1.w, BhT[kp][4*n4+3], BlT[kp][4*n4+3]);
        }
        __syncthreads();
        #pragma unroll
        for (int c16 = 0; c16 < 2; c16++) {
            int coff = c16 * 8;
            uint32_t ah[2][4], al[2][4];
            #pragma unroll
            for (int mt = 0; mt < 2; mt++) {
                int m0 = wm + mt*16;
                ah[mt][0] = Ah[m0 + g    ][coff + tg    ];
                ah[mt][1] = Ah[m0 + g + 8][coff + tg    ];
                ah[mt][2] = Ah[m0 + g    ][coff + tg + 4];
                ah[mt][3] = Ah[m0 + g + 8][coff + tg + 4];
                al[mt][0] = Al[m0 + g    ][coff + tg    ];
                al[mt][1] = Al[m0 + g + 8][coff + tg    ];
                al[mt][2] = Al[m0 + g    ][coff + tg + 4];
                al[mt][3] = Al[m0 + g + 8][coff + tg + 4];
            }
            #pragma unroll
            for (int nt = 0; nt < 8; nt++) {
                int n0 = wn + nt*8 + g;
                uint32_t bh[2], bl[2];
                bh[0] = BhT[coff + tg    ][n0];
                bh[1] = BhT[coff + tg + 4][n0];
                bl[0] = BlT[coff + tg    ][n0];
                bl[1] = BlT[coff + tg + 4][n0];
                #pragma unroll
                for (int mt = 0; mt < 2; mt++) {
                    mma_bf16(c[mt][nt], ah[mt], bh);
                    mma_bf16(c[mt][nt], ah[mt], bl);
                    mma_bf16(c[mt][nt], al[mt], bh);
                }
            }
        }
        __syncthreads();
    }

    // epilogue: wv * gate -> g_wvg[(b*512+l)*1024 + h*128 + dv]
    #pragma unroll
    for (int mt = 0; mt < 2; mt++) {
        int row = row0 + wm + mt*16 + g;
        #pragma unroll
        for (int nt = 0; nt < 8; nt++) {
            int col = wn + nt*8 + tg*2;
            size_t o0 = ((size_t)(b*Ll + row))*1024 + h*128 + col;
            size_t o1 = ((size_t)(b*Ll + row + 8))*1024 + h*128 + col;
            float2 g0 = *(const float2*)&g_g[o0];
            float2 g1 = *(const float2*)&g_g[o1];
            *(float2*)&g_wvg[o0] = make_float2(c[mt][nt][0]*g0.x, c[mt][nt][1]*g0.y);
            *(float2*)&g_wvg[o1] = make_float2(c[mt][nt][2]*g1.x, c[mt][nt][3]*g1.y);
        }
    }
}

// ---------------- 3) per-head LN of q and k, qu/qv, v copy, gate -------------
__global__ void qkln_kernel(const float* __restrict__ xu, const float* __restrict__ xv) {
    __shared__ float sh[4];
    int bl = blockIdx.x, h = blockIdx.y, t = threadIdx.x;
    int b = bl >> 9, l = bl & 511;
    size_t bh = (size_t)(b*Hh + h);

    float x  = g_qraw[(size_t)bl*1024 + h*128 + t];
    float mu = blockReduceSum128(x, sh) * (1.f/128.f);
    float d  = x - mu;
    float var = blockReduceSum128(d*d, sh) * (1.f/128.f);
    float qn = d * rsqrtf(var + 1e-6f);
    g_qu[(bh*Ll + l)*128 + t] = qn + xu[h*128 + t];
    g_qv[(bh*Ll + l)*128 + t] = qn + xv[h*128 + t];

    x  = g_kvg[(size_t)bl*3072 + h*128 + t];
    mu = blockReduceSum128(x, sh) * (1.f/128.f);
    d  = x - mu;
    var = blockReduceSum128(d*d, sh) * (1.f/128.f);
    g_kn[(bh*Ll + l)*128 + t] = d * rsqrtf(var + 1e-6f);

    g_vals[(bh*WTOT + Mm + l)*128 + t] = g_kvg[(size_t)bl*3072 + 1024 + h*128 + t];

    float gx = g_kvg[(size_t)bl*3072 + 2048 + h*128 + t];
    g_g[(size_t)bl*1024 + h*128 + t] = gx / (1.f + __expf(-gx));
}

// ---------------- 4) VQ argmin over 512 codes --------------------------------
__global__ void vq_kernel(const float* __restrict__ codebook) {
    __shared__ float ks[16][128];
    __shared__ float redv[16][256];
    __shared__ int   redi[16][256];
    int bh = blockIdx.x, lt = blockIdx.y;
    int h  = bh & 7;
    int tid = threadIdx.x;
    #pragma unroll
    for (int j = 0; j < 2; j++) {
        int f = tid + j*256;
        int r = f >> 5, c4 = f & 31;
        *(float4*)&ks[r][c4*4] =
            *(const float4*)&g_kn[((size_t)bh*Ll + lt*16 + r)*128 + c4*4];
    }
    __syncthreads();

    float best[16]; int bidx[16];
    #pragma unroll
    for (int r = 0; r < 16; r++) { best[r] = 3.4e38f; bidx[r] = 0; }

    for (int s = tid; s < Ss; s += 256) {
        const float4* c = (const float4*)(codebook + ((size_t)h*Ss + s)*128);
        float cc = 0.f; float acc[16];
        #pragma unroll
        for (int r = 0; r < 16; r++) acc[r] = 0.f;
        #pragma unroll 4
        for (int d4 = 0; d4 < 32; d4++) {
            float4 cv = c[d4];
            cc += cv.x*cv.x + cv.y*cv.y + cv.z*cv.z + cv.w*cv.w;
            #pragma unroll
            for (int r = 0; r < 16; r++) {
                float4 kv = *(float4*)&ks[r][d4*4];
                acc[r] += cv.x*kv.x + cv.y*kv.y + cv.z*kv.z + cv.w*kv.w;
            }
        }
        #pragma unroll
        for (int r = 0; r < 16; r++) {
            float d2 = cc - 2.f*acc[r];
            if (d2 < best[r]) { best[r] = d2; bidx[r] = s; }
        }
    }
    #pragma unroll
    for (int r = 0; r < 16; r++) { redv[r][tid] = best[r]; redi[r][tid] = bidx[r]; }
    __syncthreads();

    int warp = tid >> 5, lane = tid & 31;
    for (int r = warp*2; r < warp*2 + 2; r++) {
        float bv = 3.4e38f; int bi = 0x7fffffff;
        for (int t = lane; t < 256; t += 32) {
            float v = redv[r][t]; int i = redi[r][t];
            if (v < bv || (v == bv && i < bi)) { bv = v; bi = i; }
        }
        #pragma unroll
        for (int o = 16; o > 0; o >>= 1) {
            float ov = __shfl_xor_sync(0xffffffffu, bv, o);
            int   oi = __shfl_xor_sync(0xffffffffu, bi, o);
            if (ov < bv || (ov == bv && oi < bi)) { bv = ov; bi = oi; }
        }
        if (lane == 0) g_z[(size_t)bh*Ll + lt*16 + r] = bi;
    }
}

// ---------------- 5) assemble keys / vals ------------------------------------
__global__ void assemble_kernel(const float* __restrict__ xlk, const float* __restrict__ xlv,
                                const float* __restrict__ codebook,
                                const float* __restrict__ aggU) {
    for (int e = blockIdx.x*blockDim.x + threadIdx.x; e < Bb*Hh*Mm*DKk;
         e += gridDim.x*blockDim.x) {
        int bh  = e >> 16;
        int rem = e & 65535;
        int m = rem >> 7, d = rem & 127;
        g_keys[((size_t)bh*WTOT + m)*128 + d] = xlk[e];
        g_vals[((size_t)bh*WTOT + m)*128 + d] = xlv[e];
        int s = g_z[(size_t)bh*Ll + m];
        int h = bh & 7;
        g_keys[((size_t)bh*WTOT + Mm + m)*128 + d] = codebook[((size_t)h*Ss + s)*128 + d];
        g_keys[((size_t)bh*WTOT + WREC + m)*128 + d] = codebook[((size_t)h*Ss + m)*128 + d];
        g_vals[((size_t)bh*WTOT + WREC + m)*128 + d] = aggU[e];
    }
}

// ---------------- 6) softmax: combine AC + shifted BD + cache bias -----------
__global__ void softmax_kernel(const float* __restrict__ aggL) {
    __shared__ float red[4];
    int l = blockIdx.x, z = blockIdx.y, tid = threadIdx.x;
    float* S1row = g_S1 + ((size_t)z*Ll + l)*WTOT;
    const float* S2row = g_S2 + ((size_t)z*Ll + l)*WREC;
    int limit = l + Mm;

    float sv[12];
    float m = -3.4e38f;
    #pragma unroll
    for (int i = 0; i < 12; i++) {
        int w = tid + i*128;
        float s;
        if (w < WREC) {
            s = (w <= limit) ? (S1row[w] + S2row[w + 511 - l]) * INVTAU : -3.4e38f;
        } else {
            float al = aggL[(size_t)z*Ss + (w - WREC)];
            float bias = (al > 0.f) ? logf(fmaxf(al, 1e-30f)) : -1e30f;
            s = S1row[w] * INVTAU + bias;
        }
        sv[i] = s;
        m = fmaxf(m, s);
    }
    #pragma unroll
    for (int o = 16; o > 0; o >>= 1) m = fmaxf(m, __shfl_xor_sync(0xffffffffu, m, o));
    if ((tid & 31) == 0) red[tid >> 5] = m;
    __syncthreads();
    m = fmaxf(fmaxf(red[0], red[1]), fmaxf(red[2], red[3]));
    __syncthreads();

    float ssum = 0.f;
    #pragma unroll
    for (int i = 0; i < 12; i++) {
        float p = (sv[i] > -1e37f) ? __expf(sv[i] - m) : 0.f;
        sv[i] = p;
        ssum += p;
    }
    #pragma unroll
    for (int o = 16; o > 0; o >>= 1) ssum += __shfl_xor_sync(0xffffffffu, ssum, o);
    if ((tid & 31) == 0) red[tid >> 5] = ssum;
    __syncthreads();
    float invd = 1.f / (red[0] + red[1] + red[2] + red[3]);

    #pragma unroll
    for (int i = 0; i < 12; i++) S1row[tid + i*128] = sv[i] * invd;
}

// ---------------- launch ------------------------------------------------------
extern "C" void kernel_launch(void* const* d_in, const int* in_sizes, int n_in,
                              void* d_out, int out_size) {
    const float* input = (const float*)d_in[0];
    const float* xlk   = (const float*)d_in[2];
    const float* xlv   = (const float*)d_in[3];
    const float* aggU  = (const float*)d_in[4];
    const float* aggL  = (const float*)d_in[5];
    const float* Wq    = (const float*)d_in[6];
    const float* Wkvg  = (const float*)d_in[7];
    const float* Wres  = (const float*)d_in[8];
    const float* xu    = (const float*)d_in[9];
    const float* xv    = (const float*)d_in[10];
    const float* xlr   = (const float*)d_in[11];
    const float* cb    = (const float*)d_in[12];
    float* out = (float*)d_out;

    float *xt, *qraw, *kvg, *wvg, *qu, *qv, *keys, *S1, *S2;
    cudaGetSymbolAddress((void**)&xt,   g_xt);
    cudaGetSymbolAddress((void**)&qraw, g_qraw);
    cudaGetSymbolAddress((void**)&kvg,  g_kvg);
    cudaGetSymbolAddress((void**)&wvg,  g_wvg);
    cudaGetSymbolAddress((void**)&qu,   g_qu);
    cudaGetSymbolAddress((void**)&qv,   g_qv);
    cudaGetSymbolAddress((void**)&keys, g_keys);
    cudaGetSymbolAddress((void**)&S1,   g_S1);
    cudaGetSymbolAddress((void**)&S2,   g_S2);

    ln_input_kernel<<<Bb*Ll, 256>>>(input);
    // q projection: tf32 (continuous consumer)
    gemm_tf32_kernel<<<dim3(1024/128, 4096/128), 256>>>(xt, Wq, qraw, 4096, 1024, 1024);
    // kvg: k columns fp32 (feeds discrete VQ argmin); v,g columns tf32
    gemm_ffma_kernel<<<dim3(1024/128, 4096/128), 256>>>(xt, Wkvg, kvg, 4096, 3072, 1024);
    gemm_tf32_kernel<<<dim3(2048/128, 4096/128), 256>>>(xt, Wkvg + 1024, kvg + 1024,
                                                        4096, 3072, 1024);
    qkln_kernel<<<dim3(Bb*Ll, Hh), 128>>>(xu, xv);
    vq_kernel<<<dim3(Bb*Hh, Ll/16), 256>>>(cb);
    assemble_kernel<<<4096, 256>>>(xlk, xlv, cb, aggU);

    // S1 = qu @ keys^T  (per bh), bf16 3-term
    gemm_ntbf_kernel<<<dim3(WTOT/128, Ll/128, 64), 256>>>(
        qu, keys, S1, WTOT,
        (size_t)Ll*128, (size_t)WTOT*128, (size_t)Ll*WTOT, 0);
    // S2 = qv @ xlr^T  (B per head), bf16 3-term
    gemm_ntbf_kernel<<<dim3(WREC/128, Ll/128, 64), 256>>>(
        qv, xlr, S2, WREC,
        (size_t)Ll*128, (size_t)WREC*128, (size_t)Ll*WREC, 1);

    softmax_kernel<<<dim3(Ll, 64), 128>>>(aggL);

    // wv = P @ vals, bf16 3-term, gated epilogue
    gemm_valbf_kernel<<<dim3(1, Ll/128, 64), 256>>>();

    gemm_tf32_kernel<<<dim3(1024/128, 4096/128), 256>>>(wvg, Wres, out, 4096, 1024, 1024);
}

// round 8
// speedup vs baseline: 5.8496x; 1.0224x over previous
#include <cuda_runtime.h>
#include <cuda_bf16.h>
#include <math.h>
#include <stdint.h>

// Shapes (fixed for this problem)
#define Bb   8
#define Ll   512
#define Mm   512
#define Hh   8
#define DKk  128
#define DVv  128
#define Ss   512
#define DMm  1024
#define WREC 1024
#define WTOT 1536    // recent 1024 + cache 512

#define INVTAU 0.08838834764831845f   // 1/sqrt(128)

// ---------------- scratch (device globals; no allocation allowed) ------------
__device__ float g_xt  [Bb*Ll*DMm];
__device__ float g_qraw[Bb*Ll*Hh*DKk];
__device__ float g_kvg [Bb*Ll*3072];
__device__ float g_kn  [Bb*Hh*Ll*DKk];
__device__ float g_g   [Bb*Ll*Hh*DVv];
__device__ float g_qu  [64*Ll*DKk];          // q + x_u  (b,h,l,d)
__device__ float g_qv  [64*Ll*DKk];          // q + x_v
__device__ float g_keys[64*WTOT*DKk];        // [xl_k_hat; c_z gather; codebook]
__device__ float g_vals[64*WTOT*DVv];        // [xl_v; v; agg_upper]
__device__ float g_S1  [(size_t)64*Ll*WTOT]; // scores -> probs
__device__ float g_S2  [(size_t)64*Ll*WREC]; // BD term
__device__ float g_wvg [Bb*Ll*Hh*DVv];
__device__ int   g_z   [Bb*Hh*Ll];

// ---------------- helpers ----------------------------------------------------
__device__ __forceinline__ float to_tf32(float x) {
    uint32_t u;
    asm("cvt.rna.tf32.f32 %0, %1;" : "=r"(u) : "f"(x));
    return __uint_as_float(u);
}

__device__ __forceinline__ void mma_tf32(float* c, const uint32_t* a, const uint32_t* b) {
    asm volatile(
        "mma.sync.aligned.m16n8k8.row.col.f32.tf32.tf32.f32 "
        "{%0,%1,%2,%3}, {%4,%5,%6,%7}, {%8,%9}, {%0,%1,%2,%3};"
        : "+f"(c[0]), "+f"(c[1]), "+f"(c[2]), "+f"(c[3])
        : "r"(a[0]), "r"(a[1]), "r"(a[2]), "r"(a[3]), "r"(b[0]), "r"(b[1]));
}

__device__ __forceinline__ void mma_bf16(float* c, const uint32_t* a, const uint32_t* b) {
    asm volatile(
        "mma.sync.aligned.m16n8k16.row.col.f32.bf16.bf16.f32 "
        "{%0,%1,%2,%3}, {%4,%5,%6,%7}, {%8,%9}, {%0,%1,%2,%3};"
        : "+f"(c[0]), "+f"(c[1]), "+f"(c[2]), "+f"(c[3])
        : "r"(a[0]), "r"(a[1]), "r"(a[2]), "r"(a[3]), "r"(b[0]), "r"(b[1]));
}

// split two floats into packed bf16x2 hi and lo words (k-pair: x->low, y->high)
__device__ __forceinline__ void split2(float x, float y, uint32_t& hi, uint32_t& lo) {
    __nv_bfloat162 h = __floats2bfloat162_rn(x, y);
    float hx = __bfloat162float(h.x), hy = __bfloat162float(h.y);
    __nv_bfloat162 l = __floats2bfloat162_rn(x - hx, y - hy);
    hi = *(uint32_t*)&h;
    lo = *(uint32_t*)&l;
}

__device__ __forceinline__ float blockReduceSum256(float v, float* sh) {
    #pragma unroll
    for (int o = 16; o > 0; o >>= 1) v += __shfl_xor_sync(0xffffffffu, v, o);
    __syncthreads();
    if ((threadIdx.x & 31) == 0) sh[threadIdx.x >> 5] = v;
    __syncthreads();
    float r = 0.f;
    #pragma unroll
    for (int i = 0; i < 8; i++) r += sh[i];
    return r;
}

__device__ __forceinline__ float blockReduceSum128(float v, float* sh) {
    #pragma unroll
    for (int o = 16; o > 0; o >>= 1) v += __shfl_xor_sync(0xffffffffu, v, o);
    __syncthreads();
    if ((threadIdx.x & 31) == 0) sh[threadIdx.x >> 5] = v;
    __syncthreads();
    return sh[0] + sh[1] + sh[2] + sh[3];
}

// ---------------- 1) LayerNorm of input (rows of 1024) -----------------------
__global__ void ln_input_kernel(const float* __restrict__ x) {
    __shared__ float sh[8];
    size_t base = (size_t)blockIdx.x * DMm;
    float lv[4]; float s = 0.f;
    #pragma unroll
    for (int j = 0; j < 4; j++) { lv[j] = x[base + threadIdx.x + j*256]; s += lv[j]; }
    float mu = blockReduceSum256(s, sh) * (1.f/1024.f);
    float s2 = 0.f;
    #pragma unroll
    for (int j = 0; j < 4; j++) { float d = lv[j] - mu; s2 += d*d; }
    float var = blockReduceSum256(s2, sh) * (1.f/1024.f);
    float rstd = rsqrtf(var + 1e-6f);
    #pragma unroll
    for (int j = 0; j < 4; j++) g_xt[base + threadIdx.x + j*256] = (lv[j]-mu)*rstd;
}

// ---------------- 2a) fp32 FFMA GEMM (full precision, k-columns) -------------
__global__ void __launch_bounds__(256, 2)
gemm_ffma_kernel(const float* __restrict__ A, const float* __restrict__ B,
                 float* __restrict__ C, int M, int N, int K) {
    __shared__ float As[16][132];
    __shared__ float Bs[16][132];
    int tid  = threadIdx.x;
    int row0 = blockIdx.y * 128;
    int col0 = blockIdx.x * 128;
    int tx = tid & 15, ty = tid >> 4;

    float acc[8][8];
    #pragma unroll
    for (int i = 0; i < 8; i++)
        #pragma unroll
        for (int j = 0; j < 8; j++) acc[i][j] = 0.f;

    for (int k0 = 0; k0 < K; k0 += 16) {
        #pragma unroll
        for (int i = 0; i < 2; i++) {
            int f = tid + i*256;
            int r = f >> 2, c4 = f & 3;
            float4 v = *(const float4*)&A[(size_t)(row0 + r)*K + k0 + c4*4];
            As[c4*4+0][r] = v.x; As[c4*4+1][r] = v.y;
            As[c4*4+2][r] = v.z; As[c4*4+3][r] = v.w;
        }
        #pragma unroll
        for (int i = 0; i < 2; i++) {
            int f = tid + i*256;
            int r = f >> 5, c4 = f & 31;
            *(float4*)&Bs[r][c4*4] = *(const float4*)&B[(size_t)(k0 + r)*N + col0 + c4*4];
        }
        __syncthreads();
        #pragma unroll
        for (int kk = 0; kk < 16; kk++) {
            float a[8], bb[8];
            *(float4*)&a[0]  = *(float4*)&As[kk][ty*8];
            *(float4*)&a[4]  = *(float4*)&As[kk][ty*8 + 4];
            *(float4*)&bb[0] = *(float4*)&Bs[kk][tx*4];
            *(float4*)&bb[4] = *(float4*)&Bs[kk][64 + tx*4];
            #pragma unroll
            for (int i = 0; i < 8; i++)
                #pragma unroll
                for (int j = 0; j < 8; j++) acc[i][j] += a[i]*bb[j];
        }
        __syncthreads();
    }
    #pragma unroll
    for (int i = 0; i < 8; i++) {
        size_t crow = (size_t)(row0 + ty*8 + i)*N;
        *(float4*)&C[crow + col0 + tx*4]      = make_float4(acc[i][0], acc[i][1], acc[i][2], acc[i][3]);
        *(float4*)&C[crow + col0 + 64 + tx*4] = make_float4(acc[i][4], acc[i][5], acc[i][6], acc[i][7]);
    }
}

// ---------------- 2b) tf32 1-term GEMM (continuous projections) --------------
__global__ void __launch_bounds__(256, 2)
gemm_tf32_kernel(const float* __restrict__ A, const float* __restrict__ B,
                 float* __restrict__ C, int M, int N, int K) {
    __shared__ float As[128][36];
    __shared__ float Bs[32][132];
    int tid  = threadIdx.x;
    int warp = tid >> 5, lane = tid & 31;
    int g  = lane >> 2, tg = lane & 3;
    int wm = (warp >> 1) * 32;
    int wn = (warp & 1) * 64;
    int row0 = blockIdx.y * 128;
    int col0 = blockIdx.x * 128;

    float c[2][8][4];
    #pragma unroll
    for (int mt = 0; mt < 2; mt++)
        #pragma unroll
        for (int nt = 0; nt < 8; nt++)
            #pragma unroll
            for (int j = 0; j < 4; j++) c[mt][nt][j] = 0.f;

    for (int k0 = 0; k0 < K; k0 += 32) {
        #pragma unroll
        for (int i = 0; i < 4; i++) {
            int f = tid + i*256;
            int r = f >> 3, cc = (f & 7) * 4;
            float4 v = *(const float4*)&A[(size_t)(row0 + r)*K + k0 + cc];
            As[r][cc+0] = to_tf32(v.x); As[r][cc+1] = to_tf32(v.y);
            As[r][cc+2] = to_tf32(v.z); As[r][cc+3] = to_tf32(v.w);
        }
        #pragma unroll
        for (int i = 0; i < 4; i++) {
            int f = tid + i*256;
            int r = f >> 5, cc = (f & 31) * 4;
            float4 v = *(const float4*)&B[(size_t)(k0 + r)*N + col0 + cc];
            Bs[r][cc+0] = to_tf32(v.x); Bs[r][cc+1] = to_tf32(v.y);
            Bs[r][cc+2] = to_tf32(v.z); Bs[r][cc+3] = to_tf32(v.w);
        }
        __syncthreads();
        #pragma unroll
        for (int ks = 0; ks < 4; ks++) {
            int kk = ks * 8;
            uint32_t a[2][4], b[8][2];
            #pragma unroll
            for (int mt = 0; mt < 2; mt++) {
                int m0 = wm + mt*16;
                a[mt][0] = __float_as_uint(As[m0 + g    ][kk + tg    ]);
                a[mt][1] = __float_as_uint(As[m0 + g + 8][kk + tg    ]);
                a[mt][2] = __float_as_uint(As[m0 + g    ][kk + tg + 4]);
                a[mt][3] = __float_as_uint(As[m0 + g + 8][kk + tg + 4]);
            }
            #pragma unroll
            for (int nt = 0; nt < 8; nt++) {
                int n0 = wn + nt*8 + g;
                b[nt][0] = __float_as_uint(Bs[kk + tg    ][n0]);
                b[nt][1] = __float_as_uint(Bs[kk + tg + 4][n0]);
            }
            #pragma unroll
            for (int mt = 0; mt < 2; mt++)
                #pragma unroll
                for (int nt = 0; nt < 8; nt++)
                    mma_tf32(c[mt][nt], a[mt], b[nt]);
        }
        __syncthreads();
    }

    #pragma unroll
    for (int mt = 0; mt < 2; mt++) {
        int row = row0 + wm + mt*16 + g;
        #pragma unroll
        for (int nt = 0; nt < 8; nt++) {
            int col = col0 + wn + nt*8 + tg*2;
            *(float2*)&C[(size_t)row*N + col]     = make_float2(c[mt][nt][0], c[mt][nt][1]);
            *(float2*)&C[(size_t)(row+8)*N + col] = make_float2(c[mt][nt][2], c[mt][nt][3]);
        }
    }
}

// ---------------- 2c) batched NT bf16 3-term GEMM (attention scores) ---------
__global__ void __launch_bounds__(256, 2)
gemm_ntbf_kernel(const float* __restrict__ A, const float* __restrict__ B,
                 float* __restrict__ C, int N,
                 size_t strideA, size_t strideB, size_t strideC, int bPerHead) {
    __shared__ uint32_t Ah[128][20], Al[128][20], Bh[128][20], Bl[128][20];

    int z = blockIdx.z;
    const float* Az = A + (size_t)z * strideA;
    const float* Bz = B + (size_t)(bPerHead ? (z & 7) : z) * strideB;
    float* Cz = C + (size_t)z * strideC;

    int tid  = threadIdx.x;
    int warp = tid >> 5, lane = tid & 31;
    int g  = lane >> 2, tg = lane & 3;
    int wm = (warp >> 1) * 32;
    int wn = (warp & 1) * 64;
    int row0 = blockIdx.y * 128;
    int col0 = blockIdx.x * 128;

    float c[2][8][4];
    #pragma unroll
    for (int mt = 0; mt < 2; mt++)
        #pragma unroll
        for (int nt = 0; nt < 8; nt++)
            #pragma unroll
            for (int j = 0; j < 4; j++) c[mt][nt][j] = 0.f;

    for (int k0 = 0; k0 < 128; k0 += 32) {
        #pragma unroll
        for (int i = 0; i < 4; i++) {
            int f = tid + i*256;
            int r = f >> 3, q4 = f & 7;
            float4 v = *(const float4*)&Az[(size_t)(row0 + r)*128 + k0 + q4*4];
            split2(v.x, v.y, Ah[r][2*q4],   Al[r][2*q4]);
            split2(v.z, v.w, Ah[r][2*q4+1], Al[r][2*q4+1]);
        }
        #pragma unroll
        for (int i = 0; i < 4; i++) {
            int f = tid + i*256;
            int r = f >> 3, q4 = f & 7;
            float4 v = *(const float4*)&Bz[(size_t)(col0 + r)*128 + k0 + q4*4];
            split2(v.x, v.y, Bh[r][2*q4],   Bl[r][2*q4]);
            split2(v.z, v.w, Bh[r][2*q4+1], Bl[r][2*q4+1]);
        }
        __syncthreads();
        #pragma unroll
        for (int c16 = 0; c16 < 2; c16++) {
            int coff = c16 * 8;
            uint32_t ah[2][4], al[2][4];
            #pragma unroll
            for (int mt = 0; mt < 2; mt++) {
                int m0 = wm + mt*16;
                ah[mt][0] = Ah[m0 + g    ][coff + tg    ];
                ah[mt][1] = Ah[m0 + g + 8][coff + tg    ];
                ah[mt][2] = Ah[m0 + g    ][coff + tg + 4];
                ah[mt][3] = Ah[m0 + g + 8][coff + tg + 4];
                al[mt][0] = Al[m0 + g    ][coff + tg    ];
                al[mt][1] = Al[m0 + g + 8][coff + tg    ];
                al[mt][2] = Al[m0 + g    ][coff + tg + 4];
                al[mt][3] = Al[m0 + g + 8][coff + tg + 4];
            }
            #pragma unroll
            for (int nt = 0; nt < 8; nt++) {
                int n0 = wn + nt*8 + g;
                uint32_t bh[2], bl[2];
                bh[0] = Bh[n0][coff + tg    ];
                bh[1] = Bh[n0][coff + tg + 4];
                bl[0] = Bl[n0][coff + tg    ];
                bl[1] = Bl[n0][coff + tg + 4];
                #pragma unroll
                for (int mt = 0; mt < 2; mt++) {
                    mma_bf16(c[mt][nt], ah[mt], bh);
                    mma_bf16(c[mt][nt], ah[mt], bl);
                    mma_bf16(c[mt][nt], al[mt], bh);
                }
            }
        }
        __syncthreads();
    }

    #pragma unroll
    for (int mt = 0; mt < 2; mt++) {
        int row = row0 + wm + mt*16 + g;
        #pragma unroll
        for (int nt = 0; nt < 8; nt++) {
            int col = col0 + wn + nt*8 + tg*2;
            *(float2*)&Cz[(size_t)row*N + col]     = make_float2(c[mt][nt][0], c[mt][nt][1]);
            *(float2*)&Cz[(size_t)(row+8)*N + col] = make_float2(c[mt][nt][2], c[mt][nt][3]);
        }
    }
}

// ---------------- 2d) batched NN bf16 3-term value GEMM, gated epilogue ------
__global__ void __launch_bounds__(256, 2)
gemm_valbf_kernel() {
    __shared__ uint32_t Ah[128][20], Al[128][20];
    __shared__ uint32_t BhT[16][136], BlT[16][136];

    int z = blockIdx.z;
    int b = z >> 3, h = z & 7;
    const float* Az = g_S1 + (size_t)z * Ll * WTOT;
    const float* Bz = g_vals + (size_t)z * WTOT * DVv;

    int tid  = threadIdx.x;
    int warp = tid >> 5, lane = tid & 31;
    int g  = lane >> 2, tg = lane & 3;
    int wm = (warp >> 1) * 32;
    int wn = (warp & 1) * 64;
    int row0 = blockIdx.y * 128;

    float c[2][8][4];
    #pragma unroll
    for (int mt = 0; mt < 2; mt++)
        #pragma unroll
        for (int nt = 0; nt < 8; nt++)
            #pragma unroll
            for (int j = 0; j < 4; j++) c[mt][nt][j] = 0.f;

    for (int k0 = 0; k0 < WTOT; k0 += 32) {
        #pragma unroll
        for (int i = 0; i < 4; i++) {
            int f = tid + i*256;
            int r = f >> 3, q4 = f & 7;
            float4 v = *(const float4*)&Az[(size_t)(row0 + r)*WTOT + k0 + q4*4];
            split2(v.x, v.y, Ah[r][2*q4],   Al[r][2*q4]);
            split2(v.z, v.w, Ah[r][2*q4+1], Al[r][2*q4+1]);
        }
        #pragma unroll
        for (int i = 0; i < 2; i++) {
            int f = tid + i*256;
            int kp = f >> 5, n4 = f & 31;
            float4 v0 = *(const float4*)&Bz[(size_t)(k0 + 2*kp    )*128 + n4*4];
            float4 v1 = *(const float4*)&Bz[(size_t)(k0 + 2*kp + 1)*128 + n4*4];
            split2(v0.x, v1.x, BhT[kp][4*n4+0], BlT[kp][4*n4+0]);
            split2(v0.y, v1.y, BhT[kp][4*n4+1], BlT[kp][4*n4+1]);
            split2(v0.z, v1.z, BhT[kp][4*n4+2], BlT[kp][4*n4+2]);
            split2(v0.w, v1.w, BhT[kp][4*n4+3], BlT[kp][4*n4+3]);
        }
        __syncthreads();
        #pragma unroll
        for (int c16 = 0; c16 < 2; c16++) {
            int coff = c16 * 8;
            uint32_t ah[2][4], al[2][4];
            #pragma unroll
            for (int mt = 0; mt < 2; mt++) {
                int m0 = wm + mt*16;
                ah[mt][0] = Ah[m0 + g    ][coff + tg    ];
                ah[mt][1] = Ah[m0 + g + 8][coff + tg    ];
                ah[mt][2] = Ah[m0 + g    ][coff + tg + 4];
                ah[mt][3] = Ah[m0 + g + 8][coff + tg + 4];
                al[mt][0] = Al[m0 + g    ][coff + tg    ];
                al[mt][1] = Al[m0 + g + 8][coff + tg    ];
                al[mt][2] = Al[m0 + g    ][coff + tg + 4];
                al[mt][3] = Al[m0 + g + 8][coff + tg + 4];
            }
            #pragma unroll
            for (int nt = 0; nt < 8; nt++) {
                int n0 = wn + nt*8 + g;
                uint32_t bh[2], bl[2];
                bh[0] = BhT[coff + tg    ][n0];
                bh[1] = BhT[coff + tg + 4][n0];
                bl[0] = BlT[coff + tg    ][n0];
                bl[1] = BlT[coff + tg + 4][n0];
                #pragma unroll
                for (int mt = 0; mt < 2; mt++) {
                    mma_bf16(c[mt][nt], ah[mt], bh);
                    mma_bf16(c[mt][nt], ah[mt], bl);
                    mma_bf16(c[mt][nt], al[mt], bh);
                }
            }
        }
        __syncthreads();
    }

    #pragma unroll
    for (int mt = 0; mt < 2; mt++) {
        int row = row0 + wm + mt*16 + g;
        #pragma unroll
        for (int nt = 0; nt < 8; nt++) {
            int col = wn + nt*8 + tg*2;
            size_t o0 = ((size_t)(b*Ll + row))*1024 + h*128 + col;
            size_t o1 = ((size_t)(b*Ll + row + 8))*1024 + h*128 + col;
            float2 g0 = *(const float2*)&g_g[o0];
            float2 g1 = *(const float2*)&g_g[o1];
            *(float2*)&g_wvg[o0] = make_float2(c[mt][nt][0]*g0.x, c[mt][nt][1]*g0.y);
            *(float2*)&g_wvg[o1] = make_float2(c[mt][nt][2]*g1.x, c[mt][nt][3]*g1.y);
        }
    }
}

// ---------------- 3) per-head LN of q and k, qu/qv, v copy, gate -------------
__global__ void qkln_kernel(const float* __restrict__ xu, const float* __restrict__ xv) {
    __shared__ float sh[4];
    int bl = blockIdx.x, h = blockIdx.y, t = threadIdx.x;
    int b = bl >> 9, l = bl & 511;
    size_t bh = (size_t)(b*Hh + h);

    float x  = g_qraw[(size_t)bl*1024 + h*128 + t];
    float mu = blockReduceSum128(x, sh) * (1.f/128.f);
    float d  = x - mu;
    float var = blockReduceSum128(d*d, sh) * (1.f/128.f);
    float qn = d * rsqrtf(var + 1e-6f);
    g_qu[(bh*Ll + l)*128 + t] = qn + xu[h*128 + t];
    g_qv[(bh*Ll + l)*128 + t] = qn + xv[h*128 + t];

    x  = g_kvg[(size_t)bl*3072 + h*128 + t];
    mu = blockReduceSum128(x, sh) * (1.f/128.f);
    d  = x - mu;
    var = blockReduceSum128(d*d, sh) * (1.f/128.f);
    g_kn[(bh*Ll + l)*128 + t] = d * rsqrtf(var + 1e-6f);

    g_vals[(bh*WTOT + Mm + l)*128 + t] = g_kvg[(size_t)bl*3072 + 1024 + h*128 + t];

    float gx = g_kvg[(size_t)bl*3072 + 2048 + h*128 + t];
    g_g[(size_t)bl*1024 + h*128 + t] = gx / (1.f + __expf(-gx));
}

// ---------------- 4) VQ argmin over 512 codes (fp32 FFMA, proven) ------------
__global__ void vq_kernel(const float* __restrict__ codebook) {
    __shared__ float ks[16][128];
    __shared__ float redv[16][256];
    __shared__ int   redi[16][256];
    int bh = blockIdx.x, lt = blockIdx.y;
    int h  = bh & 7;
    int tid = threadIdx.x;
    #pragma unroll
    for (int j = 0; j < 2; j++) {
        int f = tid + j*256;
        int r = f >> 5, c4 = f & 31;
        *(float4*)&ks[r][c4*4] =
            *(const float4*)&g_kn[((size_t)bh*Ll + lt*16 + r)*128 + c4*4];
    }
    __syncthreads();

    float best[16]; int bidx[16];
    #pragma unroll
    for (int r = 0; r < 16; r++) { best[r] = 3.4e38f; bidx[r] = 0; }

    for (int s = tid; s < Ss; s += 256) {
        const float4* c = (const float4*)(codebook + ((size_t)h*Ss + s)*128);
        float cc = 0.f; float acc[16];
        #pragma unroll
        for (int r = 0; r < 16; r++) acc[r] = 0.f;
        #pragma unroll 4
        for (int d4 = 0; d4 < 32; d4++) {
            float4 cv = c[d4];
            cc += cv.x*cv.x + cv.y*cv.y + cv.z*cv.z + cv.w*cv.w;
            #pragma unroll
            for (int r = 0; r < 16; r++) {
                float4 kv = *(float4*)&ks[r][d4*4];
                acc[r] += cv.x*kv.x + cv.y*kv.y + cv.z*kv.z + cv.w*kv.w;
            }
        }
        #pragma unroll
        for (int r = 0; r < 16; r++) {
            float d2 = cc - 2.f*acc[r];
            if (d2 < best[r]) { best[r] = d2; bidx[r] = s; }
        }
    }
    #pragma unroll
    for (int r = 0; r < 16; r++) { redv[r][tid] = best[r]; redi[r][tid] = bidx[r]; }
    __syncthreads();

    int warp = tid >> 5, lane = tid & 31;
    for (int r = warp*2; r < warp*2 + 2; r++) {
        float bv = 3.4e38f; int bi = 0x7fffffff;
        for (int t = lane; t < 256; t += 32) {
            float v = redv[r][t]; int i = redi[r][t];
            if (v < bv || (v == bv && i < bi)) { bv = v; bi = i; }
        }
        #pragma unroll
        for (int o = 16; o > 0; o >>= 1) {
            float ov = __shfl_xor_sync(0xffffffffu, bv, o);
            int   oi = __shfl_xor_sync(0xffffffffu, bi, o);
            if (ov < bv || (ov == bv && oi < bi)) { bv = ov; bi = oi; }
        }
        if (lane == 0) g_z[(size_t)bh*Ll + lt*16 + r] = bi;
    }
}

// ---------------- 5) assemble keys / vals ------------------------------------
__global__ void assemble_kernel(const float* __restrict__ xlk, const float* __restrict__ xlv,
                                const float* __restrict__ codebook,
                                const float* __restrict__ aggU) {
    for (int e = blockIdx.x*blockDim.x + threadIdx.x; e < Bb*Hh*Mm*DKk;
         e += gridDim.x*blockDim.x) {
        int bh  = e >> 16;
        int rem = e & 65535;
        int m = rem >> 7, d = rem & 127;
        g_keys[((size_t)bh*WTOT + m)*128 + d] = xlk[e];
        g_vals[((size_t)bh*WTOT + m)*128 + d] = xlv[e];
        int s = g_z[(size_t)bh*Ll + m];
        int h = bh & 7;
        g_keys[((size_t)bh*WTOT + Mm + m)*128 + d] = codebook[((size_t)h*Ss + s)*128 + d];
        g_keys[((size_t)bh*WTOT + WREC + m)*128 + d] = codebook[((size_t)h*Ss + m)*128 + d];
        g_vals[((size_t)bh*WTOT + WREC + m)*128 + d] = aggU[e];
    }
}

// ---------------- 6) softmax: combine AC + shifted BD + cache bias -----------
__global__ void softmax_kernel(const float* __restrict__ aggL) {
    __shared__ float red[4];
    int l = blockIdx.x, z = blockIdx.y, tid = threadIdx.x;
    float* S1row = g_S1 + ((size_t)z*Ll + l)*WTOT;
    const float* S2row = g_S2 + ((size_t)z*Ll + l)*WREC;
    int limit = l + Mm;

    float sv[12];
    float m = -3.4e38f;
    #pragma unroll
    for (int i = 0; i < 12; i++) {
        int w = tid + i*128;
        float s;
        if (w < WREC) {
            s = (w <= limit) ? (S1row[w] + S2row[w + 511 - l]) * INVTAU : -3.4e38f;
        } else {
            float al = aggL[(size_t)z*Ss + (w - WREC)];
            float bias = (al > 0.f) ? logf(fmaxf(al, 1e-30f)) : -1e30f;
            s = S1row[w] * INVTAU + bias;
        }
        sv[i] = s;
        m = fmaxf(m, s);
    }
    #pragma unroll
    for (int o = 16; o > 0; o >>= 1) m = fmaxf(m, __shfl_xor_sync(0xffffffffu, m, o));
    if ((tid & 31) == 0) red[tid >> 5] = m;
    __syncthreads();
    m = fmaxf(fmaxf(red[0], red[1]), fmaxf(red[2], red[3]));
    __syncthreads();

    float ssum = 0.f;
    #pragma unroll
    for (int i = 0; i < 12; i++) {
        float p = (sv[i] > -1e37f) ? __expf(sv[i] - m) : 0.f;
        sv[i] = p;
        ssum += p;
    }
    #pragma unroll
    for (int o = 16; o > 0; o >>= 1) ssum += __shfl_xor_sync(0xffffffffu, ssum, o);
    if ((tid & 31) == 0) red[tid >> 5] = ssum;
    __syncthreads();
    float invd = 1.f / (red[0] + red[1] + red[2] + red[3]);

    #pragma unroll
    for (int i = 0; i < 12; i++) S1row[tid + i*128] = sv[i] * invd;
}

// ---------------- launch ------------------------------------------------------
extern "C" void kernel_launch(void* const* d_in, const int* in_sizes, int n_in,
                              void* d_out, int out_size) {
    const float* input = (const float*)d_in[0];
    const float* xlk   = (const float*)d_in[2];
    const float* xlv   = (const float*)d_in[3];
    const float* aggU  = (const float*)d_in[4];
    const float* aggL  = (const float*)d_in[5];
    const float* Wq    = (const float*)d_in[6];
    const float* Wkvg  = (const float*)d_in[7];
    const float* Wres  = (const float*)d_in[8];
    const float* xu    = (const float*)d_in[9];
    const float* xv    = (const float*)d_in[10];
    const float* xlr   = (const float*)d_in[11];
    const float* cb    = (const float*)d_in[12];
    float* out = (float*)d_out;

    float *xt, *qraw, *kvg, *wvg, *qu, *qv, *keys, *S1, *S2;
    cudaGetSymbolAddress((void**)&xt,   g_xt);
    cudaGetSymbolAddress((void**)&qraw, g_qraw);
    cudaGetSymbolAddress((void**)&kvg,  g_kvg);
    cudaGetSymbolAddress((void**)&wvg,  g_wvg);
    cudaGetSymbolAddress((void**)&qu,   g_qu);
    cudaGetSymbolAddress((void**)&qv,   g_qv);
    cudaGetSymbolAddress((void**)&keys, g_keys);
    cudaGetSymbolAddress((void**)&S1,   g_S1);
    cudaGetSymbolAddress((void**)&S2,   g_S2);

    // side stream + events, created once (outside any graph capture: the first
    // call is the eager correctness run). Work is identical on every call.
    static cudaStream_t sA = nullptr;
    static cudaEvent_t evFork, evKP, evQK, evVQ;
    if (sA == nullptr) {
        cudaStreamCreateWithFlags(&sA, cudaStreamNonBlocking);
        cudaEventCreateWithFlags(&evFork, cudaEventDisableTiming);
        cudaEventCreateWithFlags(&evKP,   cudaEventDisableTiming);
        cudaEventCreateWithFlags(&evQK,   cudaEventDisableTiming);
        cudaEventCreateWithFlags(&evVQ,   cudaEventDisableTiming);
    }

    // ---- stage 0: input LN (main stream) ----
    ln_input_kernel<<<Bb*Ll, 256>>>(input);
    cudaEventRecord(evFork, 0);
    cudaStreamWaitEvent(sA, evFork, 0);

    // ---- stage 1: projections. FFMA k-proj on side stream, tensor on main ----
    gemm_ffma_kernel<<<dim3(1024/128, 4096/128), 256, 0, sA>>>(xt, Wkvg, kvg,
                                                               4096, 3072, 1024);
    cudaEventRecord(evKP, sA);
    gemm_tf32_kernel<<<dim3(1024/128, 4096/128), 256>>>(xt, Wq, qraw, 4096, 1024, 1024);
    gemm_tf32_kernel<<<dim3(2048/128, 4096/128), 256>>>(xt, Wkvg + 1024, kvg + 1024,
                                                        4096, 3072, 1024);
    cudaStreamWaitEvent(0, evKP, 0);

    // ---- stage 2: per-head LN / gates (main) ----
    qkln_kernel<<<dim3(Bb*Ll, Hh), 128>>>(xu, xv);
    cudaEventRecord(evQK, 0);
    cudaStreamWaitEvent(sA, evQK, 0);

    // ---- stage 3: VQ + assemble on side stream; S2 (bf16 tensor) on main ----
    vq_kernel<<<dim3(Bb*Hh, Ll/16), 256, 0, sA>>>(cb);
    assemble_kernel<<<4096, 256, 0, sA>>>(xlk, xlv, cb, aggU);
    cudaEventRecord(evVQ, sA);
    gemm_ntbf_kernel<<<dim3(WREC/128, Ll/128, 64), 256>>>(
        qv, xlr, S2, WREC,
        (size_t)Ll*128, (size_t)WREC*128, (size_t)Ll*WREC, 1);
    cudaStreamWaitEvent(0, evVQ, 0);

    // ---- stage 4: S1, softmax, PV, output projection (main) ----
    gemm_ntbf_kernel<<<dim3(WTOT/128, Ll/128, 64), 256>>>(
        qu, keys, S1, WTOT,
        (size_t)Ll*128, (size_t)WTOT*128, (size_t)Ll*WTOT, 0);
    softmax_kernel<<<dim3(Ll, 64), 128>>>(aggL);
    gemm_valbf_kernel<<<dim3(1, Ll/128, 64), 256>>>();
    gemm_tf32_kernel<<<dim3(1024/128, 4096/128), 256>>>(wvg, Wres, out, 4096, 1024, 1024);
}